// round 10
// baseline (speedup 1.0000x reference)
#include <cuda_runtime.h>
#include <math.h>

#define Bn   4
#define CIN  256
#define CE   64
#define Gn   4
#define Hn   80
#define Wn   80
#define Nn   (Hn*Wn)        // 6400
#define NCH  65             // channel chunks of 4 (16 per group + 1 norm chunk)
#define NS   8              // table slots: strides 1,2,4,8,16,32,64,128
#define EPSV 1e-8f
#define TUU  1024           // threads for k_up
#define QUU  7              // ceil(Nn/TUU)
#define TD   512            // threads for k_down

// ---------------- static device scratch ----------------
__device__ float  g_ft   [Bn*Nn*CIN];     // feature transposed (b, n, c)
__device__ float  g_embt [Bn*Nn*CE];
__device__ float  g_gembt[Bn*Nn*CE];
__device__ float  g_conf [Bn*Nn*Gn];      // (b, n, g)
__device__ float  g_w    [Bn*Gn*Nn];      // (b, g, k) BFS order
__device__ float4 g_cC   [Bn*NCH*Nn];     // chunked scan data [b][chunk][k]
__device__ float4 g_jm4  [Bn*NS*Nn];      // multipliers float4 [b][slot][k] (norm chunk)
__device__ float  g_jmP  [Bn*NS*Gn*Nn];   // multipliers planar [b][slot][g][k]
__device__ int    g_janc [Bn*NS*Nn];      // ancestors [b][slot][k]
__device__ int    g_rs   [Bn*NS*Nn];      // descendant-range start
__device__ int    g_re   [Bn*NS*Nn];      // descendant-range end
__device__ int    g_inv  [Bn*Nn];
__device__ int    g_ls   [Bn*(Nn+2)];
__device__ int    g_nlvl [Bn];

// ---------------- packed f32x2 FMA ----------------
__device__ __forceinline__ void ffma2(unsigned long long &d,
                                      unsigned long long a,
                                      unsigned long long b) {
    asm("fma.rn.f32x2 %0, %1, %2, %0;" : "+l"(d) : "l"(a), "l"(b));
}

// ---------------- K1: skinny GEMMs via packed f32x2 FMA ----------------
__global__ __launch_bounds__(256) void k_gemm(const float* __restrict__ feat,
                                              const float* __restrict__ guide,
                                              const float* __restrict__ We,
                                              const float* __restrict__ Wc,
                                              const float* __restrict__ Wg) {
    __shared__ char smraw[34816];
    float*  xs = reinterpret_cast<float*>(smraw);
    float2* ws = reinterpret_cast<float2*>(smraw + 16384);
    float*  stage = reinterpret_cast<float*>(smraw);

    int tid = threadIdx.x;
    int os = tid >> 5;
    int nq = tid & 31;
    int n0 = blockIdx.x * 128;
    int b  = blockIdx.y;
    int path = blockIdx.z;

    const float* X = (path == 0 ? feat : guide) + (size_t)b * CIN * Nn;

    unsigned long long acc[9][2];
#pragma unroll
    for (int j = 0; j < 9; ++j) { acc[j][0] = 0ull; acc[j][1] = 0ull; }

    for (int kc = 0; kc < 256; kc += 32) {
        const float* Xb = X + (size_t)kc * Nn + n0;
#pragma unroll
        for (int i = tid; i < 1024; i += 256) {
            int kk = i >> 5, c4 = i & 31;
            *reinterpret_cast<float4*>(&xs[kk * 128 + c4 * 4]) =
                *reinterpret_cast<const float4*>(&Xb[(size_t)kk * Nn + c4 * 4]);
        }
#pragma unroll
        for (int i = tid; i < 2304; i += 256) {
            int o = i >> 5, kk = i & 31;
            float v = 0.f;
            if (path == 0) {
                if (o < 64)       v = We[o * 256 + kc + kk];
                else if (o < 68)  v = Wc[(o - 64) * 256 + kc + kk];
            } else {
                if (o < 64)       v = Wg[o * 256 + kc + kk];
            }
            ws[i] = make_float2(v, v);
        }
        __syncthreads();
#pragma unroll 2
        for (int kk = 0; kk < 32; ++kk) {
            float4 x4 = *reinterpret_cast<const float4*>(&xs[kk * 128 + nq * 4]);
            unsigned long long xlo = *reinterpret_cast<unsigned long long*>(&x4.x);
            unsigned long long xhi = *reinterpret_cast<unsigned long long*>(&x4.z);
#pragma unroll
            for (int j = 0; j < 9; ++j) {
                float2 wv = ws[(os * 9 + j) * 32 + kk];
                unsigned long long wp = *reinterpret_cast<unsigned long long*>(&wv);
                ffma2(acc[j][0], xlo, wp);
                ffma2(acc[j][1], xhi, wp);
            }
        }
        __syncthreads();
    }
#pragma unroll
    for (int j = 0; j < 9; ++j) {
        int o = os * 9 + j;
        if (o < 68) {
            float2 lo = *reinterpret_cast<float2*>(&acc[j][0]);
            float2 hi = *reinterpret_cast<float2*>(&acc[j][1]);
            stage[(nq * 4 + 0) * 68 + o] = lo.x;
            stage[(nq * 4 + 1) * 68 + o] = lo.y;
            stage[(nq * 4 + 2) * 68 + o] = hi.x;
            stage[(nq * 4 + 3) * 68 + o] = hi.y;
        }
    }
    __syncthreads();
    float* outt = (path == 0) ? g_embt : g_gembt;
#pragma unroll
    for (int i = tid; i < 2048; i += 256) {
        int n = i >> 4, c4 = i & 15;
        float4 v = *reinterpret_cast<float4*>(&stage[n * 68 + c4 * 4]);
        *reinterpret_cast<float4*>(&outt[((size_t)b * Nn + n0 + n) * 64 + c4 * 4]) = v;
    }
    if (path == 0) {
#pragma unroll
        for (int i = tid; i < 512; i += 256) {
            int n = i >> 2, gg = i & 3;
            float x = stage[n * 68 + 64 + gg];
            g_conf[((size_t)b * Nn + n0 + n) * 4 + gg] = 1.f / (1.f + expf(-x));
        }
    }
}

// ---------------- K2: edge weights, 2 threads per node ----------------
__global__ __launch_bounds__(256) void k_w(const int* __restrict__ order,
                                           const int* __restrict__ parent,
                                           const float* __restrict__ beta) {
    int b = blockIdx.y;
    int idx = blockIdx.x * 256 + threadIdx.x;
    int k = idx >> 1, half = idx & 1;
    if (k >= Nn) return;
    int n1 = order[b * Nn + k];
    int p  = parent[b * Nn + k];
    int n0 = order[b * Nn + p];
    int coff = half * 32;
    const float4* e1 = reinterpret_cast<const float4*>(g_embt  + ((size_t)b * Nn + n1) * 64 + coff);
    const float4* e0 = reinterpret_cast<const float4*>(g_embt  + ((size_t)b * Nn + n0) * 64 + coff);
    const float4* q1 = reinterpret_cast<const float4*>(g_gembt + ((size_t)b * Nn + n1) * 64 + coff);
    const float4* q0 = reinterpret_cast<const float4*>(g_gembt + ((size_t)b * Nn + n0) * 64 + coff);
    float d[2] = {0.f, 0.f};
#pragma unroll
    for (int i = 0; i < 8; ++i) {
        float4 a = e1[i], c = e0[i];
        float dx = a.x - c.x, dy = a.y - c.y, dz = a.z - c.z, dw = a.w - c.w;
        d[i >> 2] += dx * dx + dy * dy + dz * dz + dw * dw;
    }
#pragma unroll
    for (int i = 0; i < 8; ++i) {
        float4 a = q1[i], c = q0[i];
        float dx = a.x - c.x, dy = a.y - c.y, dz = a.z - c.z, dw = a.w - c.w;
        d[i >> 2] += dx * dx + dy * dy + dz * dz + dw * dw;
    }
#pragma unroll
    for (int j = 0; j < 2; ++j) {
        int g = half * 2 + j;
        float bb = beta[g];
        g_w[((size_t)b * 4 + g) * Nn + k] = expf(-(d[j] + bb * bb));
    }
}

// ---------------- K3: fused transpose + levels + jump tables/ranges (8 slots) ----------------
__global__ __launch_bounds__(256) void k_pretab(const float* __restrict__ feat,
                                                const int* __restrict__ order,
                                                const int* __restrict__ parent) {
    extern __shared__ int sh[];
    int bid = blockIdx.x;
    int tid = threadIdx.x;

    if (bid < 6400) {
        __shared__ float t[32][33];
        int b = bid / 1600;
        int r2 = bid - b * 1600;
        int c0 = (r2 / 200) * 32;
        int n0 = (r2 % 200) * 32;
        int tx = tid & 31, ty = tid >> 5;
        const float* src = feat + ((size_t)b * CIN + c0) * Nn + n0;
#pragma unroll
        for (int r = 0; r < 32; r += 8)
            t[ty + r][tx] = src[(size_t)(ty + r) * Nn + tx];
        __syncthreads();
        float* dst = g_ft + ((size_t)b * Nn + n0) * CIN + c0;
#pragma unroll
        for (int r = 0; r < 32; r += 8)
            dst[(size_t)(ty + r) * CIN + tx] = t[tx][ty + r];
        return;
    }

    if (bid < 6404) {
        int* a0 = sh;
        int* a1 = sh + Nn;
        int* l0 = sh + 2 * Nn;
        int* l1 = sh + 3 * Nn;
        __shared__ int s_more;
        int b = bid - 6400;
        const int* pp = parent + b * Nn;
        const int* od = order + b * Nn;
        for (int k = tid; k < Nn; k += 256) {
            a0[k] = pp[k];
            l0[k] = (k == 0) ? 0 : 1;
            g_inv[b * Nn + od[k]] = k;
        }
        __syncthreads();
        int* aa = a0; int* ab = a1; int* la = l0; int* lb = l1;
        for (int it = 0; it < 13; ++it) {
            if (tid == 0) s_more = 0;
            __syncthreads();
            int any = 0;
            for (int k = tid; k < Nn; k += 256) {
                int a = aa[k];
                lb[k] = la[k] + la[a];
                int na = aa[a];
                ab[k] = na;
                any |= na;
            }
            if (any) s_more = 1;
            __syncthreads();
            int* tmp = aa; aa = ab; ab = tmp;
            tmp = la; la = lb; lb = tmp;
            if (!s_more) break;
        }
        int* ls = g_ls + b * (Nn + 2);
        for (int k = tid; k < Nn; k += 256) {
            if (k == 0) ls[0] = 0;
            else if (la[k] != la[k - 1]) ls[la[k]] = k;
            if (k == Nn - 1) { g_nlvl[b] = la[k] + 1; ls[la[k] + 1] = Nn; }
        }
        return;
    }

    // -------- tables role: slots 0..7 = strides 1,2,4,...,128 --------
    {
        int b = bid - 6404;
        const int* pp = parent + b * Nn;
        int*    anc = g_janc + (size_t)b * NS * Nn;
        float4* jm4 = g_jm4  + (size_t)b * NS * Nn;
        for (int k = tid; k < Nn; k += 256) {
            anc[k] = pp[k];
            float4 mv;
            mv.x = (k == 0) ? 0.f : g_w[((size_t)b * 4 + 0) * Nn + k];
            mv.y = (k == 0) ? 0.f : g_w[((size_t)b * 4 + 1) * Nn + k];
            mv.z = (k == 0) ? 0.f : g_w[((size_t)b * 4 + 2) * Nn + k];
            mv.w = (k == 0) ? 0.f : g_w[((size_t)b * 4 + 3) * Nn + k];
            jm4[k] = mv;
        }
        __syncthreads();
        for (int s = 1; s < NS; ++s) {
            for (int k = tid; k < Nn; k += 256) {
                int a = anc[(s - 1) * Nn + k];
                anc[s * Nn + k] = anc[(s - 1) * Nn + a];
                float4 mk = jm4[(s - 1) * Nn + k];
                float4 ma = jm4[(s - 1) * Nn + a];
                float4 mo;
                mo.x = mk.x * ma.x; mo.y = mk.y * ma.y;
                mo.z = mk.z * ma.z; mo.w = mk.w * ma.w;
                jm4[s * Nn + k] = mo;
            }
            __syncthreads();
        }
        float* jmP = g_jmP + (size_t)b * NS * Gn * Nn;
        for (int s = 0; s < NS; ++s) {
            for (int k = tid; k < Nn; k += 256) {
                float4 m = jm4[s * Nn + k];
                jmP[(s * Gn + 0) * Nn + k] = m.x;
                jmP[(s * Gn + 1) * Nn + k] = m.y;
                jmP[(s * Gn + 2) * Nn + k] = m.z;
                jmP[(s * Gn + 3) * Nn + k] = m.w;
            }
        }
        int* rs = g_rs + (size_t)b * NS * Nn;
        int* re = g_re + (size_t)b * NS * Nn;
        for (int i = tid; i < NS * Nn; i += 256) { rs[i] = 0; re[i] = 0; }
        __syncthreads();
        for (int s = 0; s < NS; ++s) {
            const int* as = anc + s * Nn;
            for (int j = tid; j < Nn; j += 256) {
                int a = as[j];
                int ap = (j > 0) ? as[j - 1] : -1;
                if (a != ap) {
                    rs[s * Nn + a] = j;
                    if (j > 0) re[s * Nn + ap] = j;
                }
                if (j == Nn - 1) re[s * Nn + a] = Nn;
            }
        }
    }
}

// ---------------- K4: up-sweep — 7 factors + stride-128 tail + 7 compose ----------------
__global__ __launch_bounds__(TUU, 1) void k_up(const int* __restrict__ order) {
    extern __shared__ float4 sm[];
    __shared__ int sls[64];
    __shared__ int s_nlvl;
    int ci = blockIdx.x, b = blockIdx.y;
    bool norm = (ci == 64);
    int g = norm ? 0 : (ci >> 4);
    int qq = ci & 15;
    int tid = threadIdx.x;
    if (tid == 0) s_nlvl = g_nlvl[b];
    __syncthreads();
    int nlvl = s_nlvl;
    int nb = (nlvl + 127) / 128;
    const int* gls = g_ls + b * (Nn + 2);
    for (int i = tid; i <= nb; i += TUU) {
        int lev = 128 * i;
        sls[i] = (lev == 0) ? 0 : ((lev >= nlvl) ? Nn : gls[lev]);
    }

    // init values in registers
    const int* od = order + b * Nn;
    float4 val[QUU];
    int ftcol = g * 64 + qq * 4;
#pragma unroll
    for (int q = 0; q < QUU; ++q) {
        int k = tid + TUU * q;
        if (k < Nn) {
            int n = od[k];
            if (!norm) {
                float cf = g_conf[((size_t)b * Nn + n) * 4 + g];
                float4 v = *reinterpret_cast<const float4*>(g_ft + ((size_t)b * Nn + n) * CIN + ftcol);
                v.x *= cf; v.y *= cf; v.z *= cf; v.w *= cf;
                val[q] = v;
            } else {
                val[q] = *reinterpret_cast<const float4*>(g_conf + ((size_t)b * Nn + n) * 4);
            }
        } else val[q] = make_float4(0.f, 0.f, 0.f, 0.f);
    }

    const int*    rsb  = g_rs   + (size_t)b * NS * Nn;
    const int*    reb  = g_re   + (size_t)b * NS * Nn;
    const int*    ancb = g_janc + (size_t)b * NS * Nn;
    const float4* m4b  = g_jm4  + (size_t)b * NS * Nn;
    const float*  mPb  = g_jmP  + (size_t)b * NS * Gn * Nn + (size_t)g * Nn;

    // ---- 7 factor passes: (I + W^sT), s = 1..64 ----
    for (int s = 0; s < 7; ++s) {
        const int* rs = rsb + s * Nn;
        const int* re = reb + s * Nn;
        __syncthreads();
#pragma unroll
        for (int q = 0; q < QUU; ++q) {
            int k = tid + TUU * q;
            if (k < Nn) {
                float4 v = val[q];
                if (!norm) {
                    float m = __ldg(&mPb[(size_t)s * Gn * Nn + k]);
                    sm[k] = make_float4(m * v.x, m * v.y, m * v.z, m * v.w);
                } else {
                    float4 m = __ldg(&m4b[s * Nn + k]);
                    sm[k] = make_float4(m.x * v.x, m.y * v.y, m.z * v.z, m.w * v.w);
                }
            }
        }
        __syncthreads();
        int lo[QUU], hi[QUU];
#pragma unroll
        for (int q = 0; q < QUU; ++q) {
            int k = tid + TUU * q;
            if (k < Nn) { lo[q] = __ldg(&rs[k]); hi[q] = __ldg(&re[k]); }
            else        { lo[q] = 0; hi[q] = 0; }
        }
#pragma unroll
        for (int q = 0; q < QUU; ++q) {
            float4 acc = val[q];
            for (int j = lo[q]; j < hi[q]; ++j) {
                float4 x = sm[j];
                acc.x += x.x; acc.y += x.y; acc.z += x.z; acc.w += x.w;
            }
            val[q] = acc;
        }
    }

    // ---- stride-128 tail solve (I - W^128T)^-1, deep -> shallow ----
    {
        const int* rs7 = rsb + 7 * Nn;
        const int* re7 = reb + 7 * Nn;
        __syncthreads();
#pragma unroll
        for (int q = 0; q < QUU; ++q) {
            int k = tid + TUU * q;
            if (k < Nn) {
                float4 v = val[q];
                if (!norm) {
                    float m = __ldg(&mPb[(size_t)7 * Gn * Nn + k]);
                    sm[k] = make_float4(m * v.x, m * v.y, m * v.z, m * v.w);
                } else {
                    float4 m = __ldg(&m4b[7 * Nn + k]);
                    sm[k] = make_float4(m.x * v.x, m.y * v.y, m.z * v.z, m.w * v.w);
                }
            }
        }
        __syncthreads();
        for (int blk = nb - 2; blk >= 0; --blk) {
            int s0 = sls[blk], e0 = sls[blk + 1];
#pragma unroll
            for (int q = 0; q < QUU; ++q) {
                int k = tid + TUU * q;
                if (k >= s0 && k < e0) {
                    float4 acc = val[q];
                    int lo = __ldg(&rs7[k]), hi = __ldg(&re7[k]);
                    for (int j = lo; j < hi; ++j) {
                        float4 x = sm[j];
                        acc.x += x.x; acc.y += x.y; acc.z += x.z; acc.w += x.w;
                    }
                    val[q] = acc;
                    if (!norm) {
                        float m = __ldg(&mPb[(size_t)7 * Gn * Nn + k]);
                        sm[k] = make_float4(m * acc.x, m * acc.y, m * acc.z, m * acc.w);
                    } else {
                        float4 m = __ldg(&m4b[7 * Nn + k]);
                        sm[k] = make_float4(m.x * acc.x, m.y * acc.y, m.z * acc.z, m.w * acc.w);
                    }
                }
            }
            __syncthreads();
        }
    }

    // ---- c1 = (1 - w^2) * agg ----
#pragma unroll
    for (int q = 0; q < QUU; ++q) {
        int k = tid + TUU * q;
        if (k < Nn) {
            if (!norm) {
                float w = __ldg(&mPb[k]);
                float f = 1.f - w * w;
                val[q].x *= f; val[q].y *= f; val[q].z *= f; val[q].w *= f;
            } else {
                float4 w = __ldg(&m4b[k]);
                val[q].x *= 1.f - w.x * w.x; val[q].y *= 1.f - w.y * w.y;
                val[q].z *= 1.f - w.z * w.z; val[q].w *= 1.f - w.w * w.w;
            }
        }
    }

    // ---- 7 compose passes: c -> c256... (c to stride 128) ----
    for (int s = 0; s < 7; ++s) {
        const int* anc = ancb + s * Nn;
        __syncthreads();
#pragma unroll
        for (int q = 0; q < QUU; ++q) {
            int k = tid + TUU * q;
            if (k < Nn) sm[k] = val[q];
        }
        __syncthreads();
#pragma unroll
        for (int q = 0; q < QUU; ++q) {
            int k = tid + TUU * q;
            if (k < Nn) {
                int a = __ldg(&anc[k]);
                float4 ca = sm[a];
                if (!norm) {
                    float m = __ldg(&mPb[(size_t)s * Gn * Nn + k]);
                    val[q].x += m * ca.x; val[q].y += m * ca.y;
                    val[q].z += m * ca.z; val[q].w += m * ca.w;
                } else {
                    float4 m = __ldg(&m4b[s * Nn + k]);
                    val[q].x += m.x * ca.x; val[q].y += m.y * ca.y;
                    val[q].z += m.z * ca.z; val[q].w += m.w * ca.w;
                }
            }
        }
    }

    float4* cc = g_cC + ((size_t)b * NCH + ci) * Nn;
#pragma unroll
    for (int q = 0; q < QUU; ++q) {
        int k = tid + TUU * q;
        if (k < Nn) cc[k] = val[q];
    }
}

// ---------------- K5: strided down-sweep (128 levels per phase) ----------------
__global__ __launch_bounds__(TD, 2) void k_down() {
    extern __shared__ float4 Z[];
    __shared__ int sls[64];
    __shared__ int s_nlvl;
    int ci = blockIdx.x, b = blockIdx.y;
    int tid = threadIdx.x;
    bool norm = (ci == 64);
    int g = norm ? 0 : (ci >> 4);

    if (tid == 0) s_nlvl = g_nlvl[b];
    __syncthreads();
    int nlvl = s_nlvl;
    int nph = (nlvl + 127) / 128;
    const int* gls = g_ls + b * (Nn + 2);
    for (int i = tid; i <= nph; i += TD) {
        int lev = 128 * i;
        sls[i] = (lev == 0) ? 0 : ((lev >= nlvl) ? Nn : gls[lev]);
    }
    __syncthreads();

    float4* cc = g_cC + ((size_t)b * NCH + ci) * Nn;
    const int* aa = g_janc + ((size_t)b * NS + 7) * Nn;
    const float4* m4 = g_jm4 + ((size_t)b * NS + 7) * Nn;
    const float* mP = g_jmP + (size_t)b * NS * Gn * Nn + (size_t)(7 * Gn + g) * Nn;

    for (int t = 0; t < nph; ++t) {
        int s0 = sls[t], e0 = sls[t + 1];
        for (int k = s0 + tid; k < e0; k += TD) {
            float4 cv = __ldg(&cc[k]);
            if (t > 0) {
                int a = __ldg(&aa[k]);
                float4 zp = Z[a];
                if (!norm) {
                    float m = __ldg(&mP[k]);
                    cv.x += m * zp.x; cv.y += m * zp.y;
                    cv.z += m * zp.z; cv.w += m * zp.w;
                } else {
                    float4 m = __ldg(&m4[k]);
                    cv.x += m.x * zp.x; cv.y += m.y * zp.y;
                    cv.z += m.z * zp.z; cv.w += m.w * zp.w;
                }
            }
            Z[k] = cv;
        }
        __syncthreads();
    }
    for (int k = tid; k < Nn; k += TD) cc[k] = Z[k];
}

// ---------------- K6: normalize + un-permute + residual ----------------
__global__ __launch_bounds__(256) void k_final(const float* __restrict__ feat,
                                               const float* __restrict__ gammap,
                                               float* __restrict__ out) {
    __shared__ float tile[32 * 65 * 4];
    __shared__ int kq[32];
    int b = blockIdx.y, n0 = blockIdx.x * 32;
    int tid = threadIdx.x;
    if (tid < 32) kq[tid] = g_inv[b * Nn + n0 + tid];
    __syncthreads();
    float4* tile4 = reinterpret_cast<float4*>(tile);
    for (int i = tid; i < 32 * 65; i += 256) {
        int r = i / 65, ci = i - r * 65;
        tile4[i] = g_cC[((size_t)b * NCH + ci) * Nn + kq[r]];
    }
    __syncthreads();
    float gamma = gammap[0];
    int nl = tid & 31;
    int cg = tid >> 5;
    for (int c = cg; c < 256; c += 8) {
        int gr = c >> 6, j = c & 63;
        float filt = tile[(nl * 65 + gr * 16 + (j >> 2)) * 4 + (j & 3)];
        float nrm  = tile[(nl * 65 + 64) * 4 + gr];
        float res = filt / (EPSV + nrm);
        size_t idx = ((size_t)b * CIN + c) * Nn + n0 + nl;
        out[idx] = fmaf(gamma, res, feat[idx]);
    }
}

// ---------------- launcher ----------------
extern "C" void kernel_launch(void* const* d_in, const int* in_sizes, int n_in,
                              void* d_out, int out_size) {
    const float* feature = (const float*)d_in[0];
    const float* guide   = (const float*)d_in[1];
    const float* We      = (const float*)d_in[2];
    const float* Wc      = (const float*)d_in[3];
    const float* Wg      = (const float*)d_in[4];
    const float* beta    = (const float*)d_in[5];
    const float* gamma   = (const float*)d_in[6];
    const int*   order   = (const int*)d_in[7];
    const int*   parent  = (const int*)d_in[8];
    float* out = (float*)d_out;

    cudaFuncSetAttribute(k_pretab, cudaFuncAttributeMaxDynamicSharedMemorySize, 4 * Nn * 4);
    cudaFuncSetAttribute(k_up,     cudaFuncAttributeMaxDynamicSharedMemorySize, Nn * 16);
    cudaFuncSetAttribute(k_down,   cudaFuncAttributeMaxDynamicSharedMemorySize, Nn * 16);

    // k_up is this module's 4th launch (ncu -s 5 profiles it)
    k_gemm<<<dim3(Nn / 128, Bn, 2), 256>>>(feature, guide, We, Wc, Wg);
    k_w<<<dim3(Nn * 2 / 256, Bn), 256>>>(order, parent, beta);
    k_pretab<<<6408, 256, 4 * Nn * 4>>>(feature, order, parent);
    k_up<<<dim3(NCH, Bn), TUU, Nn * 16>>>(order);
    k_down<<<dim3(NCH, Bn), TD, Nn * 16>>>();
    k_final<<<dim3(Nn / 32, Bn), 256>>>(feature, gamma, out);
}

// round 12
// speedup vs baseline: 1.1552x; 1.1552x over previous
#include <cuda_runtime.h>
#include <math.h>

#define Bn   4
#define CIN  256
#define CE   64
#define Gn   4
#define Hn   80
#define Wn   80
#define Nn   (Hn*Wn)        // 6400
#define NCH  65             // channel chunks of 4 (16 per group + 1 norm chunk)
#define NS   8              // table slots: strides 1,2,4,...,128
#define EPSV 1e-8f
#define TUU  1024           // threads for k_up / k_pretab
#define TD   512            // threads for k_down

// ---------------- static device scratch ----------------
__device__ float  g_ft   [Bn*Nn*CIN];
__device__ float  g_embt [Bn*Nn*CE];
__device__ float  g_gembt[Bn*Nn*CE];
__device__ float  g_conf [Bn*Nn*Gn];
__device__ float  g_w    [Bn*Gn*Nn];
__device__ float4 g_cC   [Bn*NCH*Nn];
__device__ float4 g_jm4  [Bn*NS*Nn];      // multipliers float4 [b][slot][k]
__device__ float  g_jmP  [Bn*NS*Gn*Nn];   // multipliers planar [b][slot][g][k]
__device__ int    g_janc [Bn*NS*Nn];
__device__ int    g_rs   [Bn*NS*Nn];
__device__ int    g_re   [Bn*NS*Nn];
__device__ int    g_inv  [Bn*Nn];
__device__ int    g_ls   [Bn*(Nn+2)];
__device__ int    g_nlvl [Bn];

// ---------------- packed f32x2 FMA ----------------
__device__ __forceinline__ void ffma2(unsigned long long &d,
                                      unsigned long long a,
                                      unsigned long long b) {
    asm("fma.rn.f32x2 %0, %1, %2, %0;" : "+l"(d) : "l"(a), "l"(b));
}

// ---------------- K1: skinny GEMMs via packed f32x2 FMA ----------------
__global__ __launch_bounds__(256) void k_gemm(const float* __restrict__ feat,
                                              const float* __restrict__ guide,
                                              const float* __restrict__ We,
                                              const float* __restrict__ Wc,
                                              const float* __restrict__ Wg) {
    __shared__ char smraw[34816];
    float*  xs = reinterpret_cast<float*>(smraw);
    float2* ws = reinterpret_cast<float2*>(smraw + 16384);
    float*  stage = reinterpret_cast<float*>(smraw);

    int tid = threadIdx.x;
    int os = tid >> 5;
    int nq = tid & 31;
    int n0 = blockIdx.x * 128;
    int b  = blockIdx.y;
    int path = blockIdx.z;

    const float* X = (path == 0 ? feat : guide) + (size_t)b * CIN * Nn;

    unsigned long long acc[9][2];
#pragma unroll
    for (int j = 0; j < 9; ++j) { acc[j][0] = 0ull; acc[j][1] = 0ull; }

    for (int kc = 0; kc < 256; kc += 32) {
        const float* Xb = X + (size_t)kc * Nn + n0;
#pragma unroll
        for (int i = tid; i < 1024; i += 256) {
            int kk = i >> 5, c4 = i & 31;
            *reinterpret_cast<float4*>(&xs[kk * 128 + c4 * 4]) =
                *reinterpret_cast<const float4*>(&Xb[(size_t)kk * Nn + c4 * 4]);
        }
#pragma unroll
        for (int i = tid; i < 2304; i += 256) {
            int o = i >> 5, kk = i & 31;
            float v = 0.f;
            if (path == 0) {
                if (o < 64)       v = We[o * 256 + kc + kk];
                else if (o < 68)  v = Wc[(o - 64) * 256 + kc + kk];
            } else {
                if (o < 64)       v = Wg[o * 256 + kc + kk];
            }
            ws[i] = make_float2(v, v);
        }
        __syncthreads();
#pragma unroll 2
        for (int kk = 0; kk < 32; ++kk) {
            float4 x4 = *reinterpret_cast<const float4*>(&xs[kk * 128 + nq * 4]);
            unsigned long long xlo = *reinterpret_cast<unsigned long long*>(&x4.x);
            unsigned long long xhi = *reinterpret_cast<unsigned long long*>(&x4.z);
#pragma unroll
            for (int j = 0; j < 9; ++j) {
                float2 wv = ws[(os * 9 + j) * 32 + kk];
                unsigned long long wp = *reinterpret_cast<unsigned long long*>(&wv);
                ffma2(acc[j][0], xlo, wp);
                ffma2(acc[j][1], xhi, wp);
            }
        }
        __syncthreads();
    }
#pragma unroll
    for (int j = 0; j < 9; ++j) {
        int o = os * 9 + j;
        if (o < 68) {
            float2 lo = *reinterpret_cast<float2*>(&acc[j][0]);
            float2 hi = *reinterpret_cast<float2*>(&acc[j][1]);
            stage[(nq * 4 + 0) * 68 + o] = lo.x;
            stage[(nq * 4 + 1) * 68 + o] = lo.y;
            stage[(nq * 4 + 2) * 68 + o] = hi.x;
            stage[(nq * 4 + 3) * 68 + o] = hi.y;
        }
    }
    __syncthreads();
    float* outt = (path == 0) ? g_embt : g_gembt;
#pragma unroll
    for (int i = tid; i < 2048; i += 256) {
        int n = i >> 4, c4 = i & 15;
        float4 v = *reinterpret_cast<float4*>(&stage[n * 68 + c4 * 4]);
        *reinterpret_cast<float4*>(&outt[((size_t)b * Nn + n0 + n) * 64 + c4 * 4]) = v;
    }
    if (path == 0) {
#pragma unroll
        for (int i = tid; i < 512; i += 256) {
            int n = i >> 2, gg = i & 3;
            float x = stage[n * 68 + 64 + gg];
            g_conf[((size_t)b * Nn + n0 + n) * 4 + gg] = 1.f / (1.f + expf(-x));
        }
    }
}

// ---------------- K2: edge weights, 2 threads per node ----------------
__global__ __launch_bounds__(256) void k_w(const int* __restrict__ order,
                                           const int* __restrict__ parent,
                                           const float* __restrict__ beta) {
    int b = blockIdx.y;
    int idx = blockIdx.x * 256 + threadIdx.x;
    int k = idx >> 1, half = idx & 1;
    if (k >= Nn) return;
    int n1 = order[b * Nn + k];
    int p  = parent[b * Nn + k];
    int n0 = order[b * Nn + p];
    int coff = half * 32;
    const float4* e1 = reinterpret_cast<const float4*>(g_embt  + ((size_t)b * Nn + n1) * 64 + coff);
    const float4* e0 = reinterpret_cast<const float4*>(g_embt  + ((size_t)b * Nn + n0) * 64 + coff);
    const float4* q1 = reinterpret_cast<const float4*>(g_gembt + ((size_t)b * Nn + n1) * 64 + coff);
    const float4* q0 = reinterpret_cast<const float4*>(g_gembt + ((size_t)b * Nn + n0) * 64 + coff);
    float d[2] = {0.f, 0.f};
#pragma unroll
    for (int i = 0; i < 8; ++i) {
        float4 a = e1[i], c = e0[i];
        float dx = a.x - c.x, dy = a.y - c.y, dz = a.z - c.z, dw = a.w - c.w;
        d[i >> 2] += dx * dx + dy * dy + dz * dz + dw * dw;
    }
#pragma unroll
    for (int i = 0; i < 8; ++i) {
        float4 a = q1[i], c = q0[i];
        float dx = a.x - c.x, dy = a.y - c.y, dz = a.z - c.z, dw = a.w - c.w;
        d[i >> 2] += dx * dx + dy * dy + dz * dz + dw * dw;
    }
#pragma unroll
    for (int j = 0; j < 2; ++j) {
        int g = half * 2 + j;
        float bb = beta[g];
        g_w[((size_t)b * 4 + g) * Nn + k] = expf(-(d[j] + bb * bb));
    }
}

// ---------------- K3: fused transpose + levels + jump tables (1024 threads) ----------------
__global__ __launch_bounds__(TUU) void k_pretab(const float* __restrict__ feat,
                                                const int* __restrict__ order,
                                                const int* __restrict__ parent) {
    extern __shared__ int sh[];
    int bid = blockIdx.x;
    int tid = threadIdx.x;

    if (bid < 6400) {
        // -------- transpose role: 32x32 tile, 1 element/thread --------
        __shared__ float t[32][33];
        int b = bid / 1600;
        int r2 = bid - b * 1600;
        int c0 = (r2 / 200) * 32;
        int n0 = (r2 % 200) * 32;
        int tx = tid & 31, ty = tid >> 5;   // 32 x 32
        const float* src = feat + ((size_t)b * CIN + c0) * Nn + n0;
        t[ty][tx] = src[(size_t)ty * Nn + tx];
        __syncthreads();
        float* dst = g_ft + ((size_t)b * Nn + n0) * CIN + c0;
        dst[(size_t)ty * CIN + tx] = t[tx][ty];
        return;
    }

    if (bid < 6404) {
        // -------- levels role --------
        int* a0 = sh;
        int* a1 = sh + Nn;
        int* l0 = sh + 2 * Nn;
        int* l1 = sh + 3 * Nn;
        __shared__ int s_more;
        int b = bid - 6400;
        const int* pp = parent + b * Nn;
        const int* od = order + b * Nn;
        for (int k = tid; k < Nn; k += TUU) {
            a0[k] = pp[k];
            l0[k] = (k == 0) ? 0 : 1;
            g_inv[b * Nn + od[k]] = k;
        }
        __syncthreads();
        int* aa = a0; int* ab = a1; int* la = l0; int* lb = l1;
        for (int it = 0; it < 13; ++it) {
            if (tid == 0) s_more = 0;
            __syncthreads();
            int any = 0;
            for (int k = tid; k < Nn; k += TUU) {
                int a = aa[k];
                lb[k] = la[k] + la[a];
                int na = aa[a];
                ab[k] = na;
                any |= na;
            }
            if (any) s_more = 1;
            __syncthreads();
            int* tmp = aa; aa = ab; ab = tmp;
            tmp = la; la = lb; lb = tmp;
            if (!s_more) break;
        }
        int* ls = g_ls + b * (Nn + 2);
        for (int k = tid; k < Nn; k += TUU) {
            if (k == 0) ls[0] = 0;
            else if (la[k] != la[k - 1]) ls[la[k]] = k;
            if (k == Nn - 1) { g_nlvl[b] = la[k] + 1; ls[la[k] + 1] = Nn; }
        }
        return;
    }

    // -------- tables role: slots 0..7 (strides 1..128) --------
    {
        int b = bid - 6404;
        const int* pp = parent + b * Nn;
        int*    anc = g_janc + (size_t)b * NS * Nn;
        float4* jm4 = g_jm4  + (size_t)b * NS * Nn;
        for (int k = tid; k < Nn; k += TUU) {
            anc[k] = pp[k];
            float4 mv;
            mv.x = (k == 0) ? 0.f : g_w[((size_t)b * 4 + 0) * Nn + k];
            mv.y = (k == 0) ? 0.f : g_w[((size_t)b * 4 + 1) * Nn + k];
            mv.z = (k == 0) ? 0.f : g_w[((size_t)b * 4 + 2) * Nn + k];
            mv.w = (k == 0) ? 0.f : g_w[((size_t)b * 4 + 3) * Nn + k];
            jm4[k] = mv;
        }
        __syncthreads();
        for (int s = 1; s < NS; ++s) {
            for (int k = tid; k < Nn; k += TUU) {
                int a = anc[(s - 1) * Nn + k];
                anc[s * Nn + k] = anc[(s - 1) * Nn + a];
                float4 mk = jm4[(s - 1) * Nn + k];
                float4 ma = jm4[(s - 1) * Nn + a];
                float4 mo;
                mo.x = mk.x * ma.x; mo.y = mk.y * ma.y;
                mo.z = mk.z * ma.z; mo.w = mk.w * ma.w;
                jm4[s * Nn + k] = mo;
            }
            __syncthreads();
        }
        float* jmP = g_jmP + (size_t)b * NS * Gn * Nn;
        for (int s = 0; s < NS; ++s) {
            for (int k = tid; k < Nn; k += TUU) {
                float4 m = jm4[s * Nn + k];
                jmP[(s * Gn + 0) * Nn + k] = m.x;
                jmP[(s * Gn + 1) * Nn + k] = m.y;
                jmP[(s * Gn + 2) * Nn + k] = m.z;
                jmP[(s * Gn + 3) * Nn + k] = m.w;
            }
        }
        int* rs = g_rs + (size_t)b * NS * Nn;
        int* re = g_re + (size_t)b * NS * Nn;
        for (int i = tid; i < NS * Nn; i += TUU) { rs[i] = 0; re[i] = 0; }
        __syncthreads();
        for (int s = 0; s < NS; ++s) {
            const int* as = anc + s * Nn;
            for (int j = tid; j < Nn; j += TUU) {
                int a = as[j];
                int ap = (j > 0) ? as[j - 1] : -1;
                if (a != ap) {
                    rs[s * Nn + a] = j;
                    if (j > 0) re[s * Nn + ap] = j;
                }
                if (j == Nn - 1) re[s * Nn + a] = Nn;
            }
        }
    }
}

// ---------------- K4: up-sweep — smem-primary ping-pong, 1024 threads ----------------
__global__ __launch_bounds__(TUU, 1) void k_up(const int* __restrict__ order) {
    extern __shared__ float4 smbuf[];
    float4* cur = smbuf;        // [Nn]
    float4* oth = smbuf + Nn;   // [Nn]
    __shared__ int sls[64];
    __shared__ int s_nlvl;
    int ci = blockIdx.x, b = blockIdx.y;
    bool norm = (ci == 64);
    int g = norm ? 0 : (ci >> 4);
    int qq = ci & 15;
    int tid = threadIdx.x;
    if (tid == 0) s_nlvl = g_nlvl[b];
    __syncthreads();
    int nlvl = s_nlvl;
    int nb = (nlvl + 127) / 128;
    const int* gls = g_ls + b * (Nn + 2);
    for (int i = tid; i <= nb; i += TUU) {
        int lev = 128 * i;
        sls[i] = (lev == 0) ? 0 : ((lev >= nlvl) ? Nn : gls[lev]);
    }

    // init cur
    const int* od = order + b * Nn;
    int ftcol = g * 64 + qq * 4;
    for (int k = tid; k < Nn; k += TUU) {
        int n = od[k];
        if (!norm) {
            float cf = g_conf[((size_t)b * Nn + n) * 4 + g];
            float4 v = *reinterpret_cast<const float4*>(g_ft + ((size_t)b * Nn + n) * CIN + ftcol);
            v.x *= cf; v.y *= cf; v.z *= cf; v.w *= cf;
            cur[k] = v;
        } else {
            cur[k] = *reinterpret_cast<const float4*>(g_conf + ((size_t)b * Nn + n) * 4);
        }
    }
    __syncthreads();

    const int*    rsb  = g_rs   + (size_t)b * NS * Nn;
    const int*    reb  = g_re   + (size_t)b * NS * Nn;
    const int*    ancb = g_janc + (size_t)b * NS * Nn;
    const float4* m4b  = g_jm4  + (size_t)b * NS * Nn;
    const float*  mPb  = g_jmP  + (size_t)b * NS * Gn * Nn + (size_t)g * Nn;

    // ---- 7 factor passes: publish oth = m_s * cur; gather cur += sum oth ----
    for (int s = 0; s < 7; ++s) {
        const int* rs = rsb + s * Nn;
        const int* re = reb + s * Nn;
        for (int k = tid; k < Nn; k += TUU) {
            float4 v = cur[k];
            if (!norm) {
                float m = __ldg(&mPb[(size_t)s * Gn * Nn + k]);
                oth[k] = make_float4(m * v.x, m * v.y, m * v.z, m * v.w);
            } else {
                float4 m = __ldg(&m4b[s * Nn + k]);
                oth[k] = make_float4(m.x * v.x, m.y * v.y, m.z * v.z, m.w * v.w);
            }
        }
        __syncthreads();
        for (int k = tid; k < Nn; k += TUU) {
            float4 acc = cur[k];
            int lo = __ldg(&rs[k]), hi = __ldg(&re[k]);
            for (int j = lo; j < hi; ++j) {
                float4 x = oth[j];
                acc.x += x.x; acc.y += x.y; acc.z += x.z; acc.w += x.w;
            }
            cur[k] = acc;
        }
        __syncthreads();
    }

    // ---- stride-128 tail solve, deep -> shallow ----
    {
        const int* rs7 = rsb + 7 * Nn;
        const int* re7 = reb + 7 * Nn;
        const float*  m7P = mPb + (size_t)7 * Gn * Nn;
        const float4* m74 = m4b + 7 * Nn;
        for (int k = tid; k < Nn; k += TUU) {
            float4 v = cur[k];
            if (!norm) {
                float m = __ldg(&m7P[k]);
                oth[k] = make_float4(m * v.x, m * v.y, m * v.z, m * v.w);
            } else {
                float4 m = __ldg(&m74[k]);
                oth[k] = make_float4(m.x * v.x, m.y * v.y, m.z * v.z, m.w * v.w);
            }
        }
        __syncthreads();
        for (int blk = nb - 2; blk >= 0; --blk) {
            int s0 = sls[blk], e0 = sls[blk + 1];
            for (int k = s0 + tid; k < e0; k += TUU) {
                float4 acc = cur[k];
                int lo = __ldg(&rs7[k]), hi = __ldg(&re7[k]);
                for (int j = lo; j < hi; ++j) {
                    float4 x = oth[j];
                    acc.x += x.x; acc.y += x.y; acc.z += x.z; acc.w += x.w;
                }
                cur[k] = acc;
                if (!norm) {
                    float m = __ldg(&m7P[k]);
                    oth[k] = make_float4(m * acc.x, m * acc.y, m * acc.z, m * acc.w);
                } else {
                    float4 m = __ldg(&m74[k]);
                    oth[k] = make_float4(m.x * acc.x, m.y * acc.y, m.z * acc.z, m.w * acc.w);
                }
            }
            __syncthreads();
        }
    }

    // ---- c1 = (1 - w^2) * agg (in place) ----
    for (int k = tid; k < Nn; k += TUU) {
        float4 v = cur[k];
        if (!norm) {
            float w = __ldg(&mPb[k]);
            float f = 1.f - w * w;
            v.x *= f; v.y *= f; v.z *= f; v.w *= f;
        } else {
            float4 w = __ldg(&m4b[k]);
            v.x *= 1.f - w.x * w.x; v.y *= 1.f - w.y * w.y;
            v.z *= 1.f - w.z * w.z; v.w *= 1.f - w.w * w.w;
        }
        cur[k] = v;
    }
    __syncthreads();

    // ---- 7 compose passes (ping-pong) ----
    float4* a = cur;
    float4* o = oth;
    for (int s = 0; s < 7; ++s) {
        const int* anc = ancb + s * Nn;
        for (int k = tid; k < Nn; k += TUU) {
            int av = __ldg(&anc[k]);
            float4 ck = a[k];
            float4 ca = a[av];
            if (!norm) {
                float m = __ldg(&mPb[(size_t)s * Gn * Nn + k]);
                ck.x += m * ca.x; ck.y += m * ca.y;
                ck.z += m * ca.z; ck.w += m * ca.w;
            } else {
                float4 m = __ldg(&m4b[s * Nn + k]);
                ck.x += m.x * ca.x; ck.y += m.y * ca.y;
                ck.z += m.z * ca.z; ck.w += m.w * ca.w;
            }
            o[k] = ck;
        }
        __syncthreads();
        float4* tmp = a; a = o; o = tmp;
    }

    float4* cc = g_cC + ((size_t)b * NCH + ci) * Nn;
    for (int k = tid; k < Nn; k += TUU) cc[k] = a[k];
}

// ---------------- K5: strided down-sweep (128 levels per phase) ----------------
__global__ __launch_bounds__(TD, 2) void k_down() {
    extern __shared__ float4 Z[];
    __shared__ int sls[64];
    __shared__ int s_nlvl;
    int ci = blockIdx.x, b = blockIdx.y;
    int tid = threadIdx.x;
    bool norm = (ci == 64);
    int g = norm ? 0 : (ci >> 4);

    if (tid == 0) s_nlvl = g_nlvl[b];
    __syncthreads();
    int nlvl = s_nlvl;
    int nph = (nlvl + 127) / 128;
    const int* gls = g_ls + b * (Nn + 2);
    for (int i = tid; i <= nph; i += TD) {
        int lev = 128 * i;
        sls[i] = (lev == 0) ? 0 : ((lev >= nlvl) ? Nn : gls[lev]);
    }
    __syncthreads();

    float4* cc = g_cC + ((size_t)b * NCH + ci) * Nn;
    const int* aa = g_janc + ((size_t)b * NS + 7) * Nn;
    const float4* m4 = g_jm4 + ((size_t)b * NS + 7) * Nn;
    const float* mP = g_jmP + (size_t)b * NS * Gn * Nn + (size_t)(7 * Gn + g) * Nn;

    for (int t = 0; t < nph; ++t) {
        int s0 = sls[t], e0 = sls[t + 1];
        for (int k = s0 + tid; k < e0; k += TD) {
            float4 cv = __ldg(&cc[k]);
            if (t > 0) {
                int a = __ldg(&aa[k]);
                float4 zp = Z[a];
                if (!norm) {
                    float m = __ldg(&mP[k]);
                    cv.x += m * zp.x; cv.y += m * zp.y;
                    cv.z += m * zp.z; cv.w += m * zp.w;
                } else {
                    float4 m = __ldg(&m4[k]);
                    cv.x += m.x * zp.x; cv.y += m.y * zp.y;
                    cv.z += m.z * zp.z; cv.w += m.w * zp.w;
                }
            }
            Z[k] = cv;
        }
        __syncthreads();
    }
    for (int k = tid; k < Nn; k += TD) cc[k] = Z[k];
}

// ---------------- K6: normalize + un-permute + residual ----------------
__global__ __launch_bounds__(256) void k_final(const float* __restrict__ feat,
                                               const float* __restrict__ gammap,
                                               float* __restrict__ out) {
    __shared__ float tile[32 * 65 * 4];
    __shared__ int kq[32];
    int b = blockIdx.y, n0 = blockIdx.x * 32;
    int tid = threadIdx.x;
    if (tid < 32) kq[tid] = g_inv[b * Nn + n0 + tid];
    __syncthreads();
    float4* tile4 = reinterpret_cast<float4*>(tile);
    for (int i = tid; i < 32 * 65; i += 256) {
        int r = i / 65, ci = i - r * 65;
        tile4[i] = g_cC[((size_t)b * NCH + ci) * Nn + kq[r]];
    }
    __syncthreads();
    float gamma = gammap[0];
    int nl = tid & 31;
    int cg = tid >> 5;
    for (int c = cg; c < 256; c += 8) {
        int gr = c >> 6, j = c & 63;
        float filt = tile[(nl * 65 + gr * 16 + (j >> 2)) * 4 + (j & 3)];
        float nrm  = tile[(nl * 65 + 64) * 4 + gr];
        float res = filt / (EPSV + nrm);
        size_t idx = ((size_t)b * CIN + c) * Nn + n0 + nl;
        out[idx] = fmaf(gamma, res, feat[idx]);
    }
}

// ---------------- launcher ----------------
extern "C" void kernel_launch(void* const* d_in, const int* in_sizes, int n_in,
                              void* d_out, int out_size) {
    const float* feature = (const float*)d_in[0];
    const float* guide   = (const float*)d_in[1];
    const float* We      = (const float*)d_in[2];
    const float* Wc      = (const float*)d_in[3];
    const float* Wg      = (const float*)d_in[4];
    const float* beta    = (const float*)d_in[5];
    const float* gamma   = (const float*)d_in[6];
    const int*   order   = (const int*)d_in[7];
    const int*   parent  = (const int*)d_in[8];
    float* out = (float*)d_out;

    cudaFuncSetAttribute(k_pretab, cudaFuncAttributeMaxDynamicSharedMemorySize, 4 * Nn * 4);
    cudaFuncSetAttribute(k_up,     cudaFuncAttributeMaxDynamicSharedMemorySize, 2 * Nn * 16);
    cudaFuncSetAttribute(k_down,   cudaFuncAttributeMaxDynamicSharedMemorySize, Nn * 16);

    // k_up is this module's 4th launch (ncu -s 5 profiles it)
    k_gemm<<<dim3(Nn / 128, Bn, 2), 256>>>(feature, guide, We, Wc, Wg);
    k_w<<<dim3(Nn * 2 / 256, Bn), 256>>>(order, parent, beta);
    k_pretab<<<6408, TUU, 4 * Nn * 4>>>(feature, order, parent);
    k_up<<<dim3(NCH, Bn), TUU, 2 * Nn * 16>>>(order);
    k_down<<<dim3(NCH, Bn), TD, Nn * 16>>>();
    k_final<<<dim3(Nn / 32, Bn), 256>>>(feature, gamma, out);
}

// round 13
// speedup vs baseline: 1.2549x; 1.0863x over previous
#include <cuda_runtime.h>
#include <math.h>

#define Bn   4
#define CIN  256
#define CE   64
#define Gn   4
#define Hn   80
#define Wn   80
#define Nn   (Hn*Wn)        // 6400
#define NCH  65             // output chunks: 64 feature (4ch) + 1 norm (4 groups)
#define NS   8              // table slots: strides 1,2,4,...,128
#define EPSV 1e-8f
#define TU   512            // threads for k_up / k_down
#define QU   13             // ceil(Nn/TU)
#define TP   1024           // threads for k_pretab

// ---------------- static device scratch ----------------
__device__ float  g_ft   [Bn*Nn*CIN];
__device__ float  g_embt [Bn*Nn*CE];
__device__ float  g_gembt[Bn*Nn*CE];
__device__ float  g_conf [Bn*Nn*Gn];
__device__ float  g_w    [Bn*Gn*Nn];
__device__ float4 g_cC   [Bn*NCH*Nn];
__device__ float4 g_jm4  [Bn*NS*Nn];      // multipliers float4 [b][slot][k] (k_down norm)
__device__ float  g_jmP  [Bn*NS*Gn*Nn];   // multipliers planar [b][slot][g][k]
__device__ int    g_janc [Bn*NS*Nn];
__device__ int    g_rs   [Bn*NS*Nn];
__device__ int    g_re   [Bn*NS*Nn];
__device__ int    g_inv  [Bn*Nn];
__device__ int    g_ls   [Bn*(Nn+2)];
__device__ int    g_nlvl [Bn];

// ---------------- packed f32x2 FMA ----------------
__device__ __forceinline__ void ffma2(unsigned long long &d,
                                      unsigned long long a,
                                      unsigned long long b) {
    asm("fma.rn.f32x2 %0, %1, %2, %0;" : "+l"(d) : "l"(a), "l"(b));
}

// ---------------- K1: skinny GEMMs via packed f32x2 FMA ----------------
__global__ __launch_bounds__(256) void k_gemm(const float* __restrict__ feat,
                                              const float* __restrict__ guide,
                                              const float* __restrict__ We,
                                              const float* __restrict__ Wc,
                                              const float* __restrict__ Wg) {
    __shared__ char smraw[34816];
    float*  xs = reinterpret_cast<float*>(smraw);
    float2* ws = reinterpret_cast<float2*>(smraw + 16384);
    float*  stage = reinterpret_cast<float*>(smraw);

    int tid = threadIdx.x;
    int os = tid >> 5;
    int nq = tid & 31;
    int n0 = blockIdx.x * 128;
    int b  = blockIdx.y;
    int path = blockIdx.z;

    const float* X = (path == 0 ? feat : guide) + (size_t)b * CIN * Nn;

    unsigned long long acc[9][2];
#pragma unroll
    for (int j = 0; j < 9; ++j) { acc[j][0] = 0ull; acc[j][1] = 0ull; }

    for (int kc = 0; kc < 256; kc += 32) {
        const float* Xb = X + (size_t)kc * Nn + n0;
#pragma unroll
        for (int i = tid; i < 1024; i += 256) {
            int kk = i >> 5, c4 = i & 31;
            *reinterpret_cast<float4*>(&xs[kk * 128 + c4 * 4]) =
                *reinterpret_cast<const float4*>(&Xb[(size_t)kk * Nn + c4 * 4]);
        }
#pragma unroll
        for (int i = tid; i < 2304; i += 256) {
            int o = i >> 5, kk = i & 31;
            float v = 0.f;
            if (path == 0) {
                if (o < 64)       v = We[o * 256 + kc + kk];
                else if (o < 68)  v = Wc[(o - 64) * 256 + kc + kk];
            } else {
                if (o < 64)       v = Wg[o * 256 + kc + kk];
            }
            ws[i] = make_float2(v, v);
        }
        __syncthreads();
#pragma unroll 2
        for (int kk = 0; kk < 32; ++kk) {
            float4 x4 = *reinterpret_cast<const float4*>(&xs[kk * 128 + nq * 4]);
            unsigned long long xlo = *reinterpret_cast<unsigned long long*>(&x4.x);
            unsigned long long xhi = *reinterpret_cast<unsigned long long*>(&x4.z);
#pragma unroll
            for (int j = 0; j < 9; ++j) {
                float2 wv = ws[(os * 9 + j) * 32 + kk];
                unsigned long long wp = *reinterpret_cast<unsigned long long*>(&wv);
                ffma2(acc[j][0], xlo, wp);
                ffma2(acc[j][1], xhi, wp);
            }
        }
        __syncthreads();
    }
#pragma unroll
    for (int j = 0; j < 9; ++j) {
        int o = os * 9 + j;
        if (o < 68) {
            float2 lo = *reinterpret_cast<float2*>(&acc[j][0]);
            float2 hi = *reinterpret_cast<float2*>(&acc[j][1]);
            stage[(nq * 4 + 0) * 68 + o] = lo.x;
            stage[(nq * 4 + 1) * 68 + o] = lo.y;
            stage[(nq * 4 + 2) * 68 + o] = hi.x;
            stage[(nq * 4 + 3) * 68 + o] = hi.y;
        }
    }
    __syncthreads();
    float* outt = (path == 0) ? g_embt : g_gembt;
#pragma unroll
    for (int i = tid; i < 2048; i += 256) {
        int n = i >> 4, c4 = i & 15;
        float4 v = *reinterpret_cast<float4*>(&stage[n * 68 + c4 * 4]);
        *reinterpret_cast<float4*>(&outt[((size_t)b * Nn + n0 + n) * 64 + c4 * 4]) = v;
    }
    if (path == 0) {
#pragma unroll
        for (int i = tid; i < 512; i += 256) {
            int n = i >> 2, gg = i & 3;
            float x = stage[n * 68 + 64 + gg];
            g_conf[((size_t)b * Nn + n0 + n) * 4 + gg] = 1.f / (1.f + expf(-x));
        }
    }
}

// ---------------- K2: edge weights, 2 threads per node ----------------
__global__ __launch_bounds__(256) void k_w(const int* __restrict__ order,
                                           const int* __restrict__ parent,
                                           const float* __restrict__ beta) {
    int b = blockIdx.y;
    int idx = blockIdx.x * 256 + threadIdx.x;
    int k = idx >> 1, half = idx & 1;
    if (k >= Nn) return;
    int n1 = order[b * Nn + k];
    int p  = parent[b * Nn + k];
    int n0 = order[b * Nn + p];
    int coff = half * 32;
    const float4* e1 = reinterpret_cast<const float4*>(g_embt  + ((size_t)b * Nn + n1) * 64 + coff);
    const float4* e0 = reinterpret_cast<const float4*>(g_embt  + ((size_t)b * Nn + n0) * 64 + coff);
    const float4* q1 = reinterpret_cast<const float4*>(g_gembt + ((size_t)b * Nn + n1) * 64 + coff);
    const float4* q0 = reinterpret_cast<const float4*>(g_gembt + ((size_t)b * Nn + n0) * 64 + coff);
    float d[2] = {0.f, 0.f};
#pragma unroll
    for (int i = 0; i < 8; ++i) {
        float4 a = e1[i], c = e0[i];
        float dx = a.x - c.x, dy = a.y - c.y, dz = a.z - c.z, dw = a.w - c.w;
        d[i >> 2] += dx * dx + dy * dy + dz * dz + dw * dw;
    }
#pragma unroll
    for (int i = 0; i < 8; ++i) {
        float4 a = q1[i], c = q0[i];
        float dx = a.x - c.x, dy = a.y - c.y, dz = a.z - c.z, dw = a.w - c.w;
        d[i >> 2] += dx * dx + dy * dy + dz * dz + dw * dw;
    }
#pragma unroll
    for (int j = 0; j < 2; ++j) {
        int g = half * 2 + j;
        float bb = beta[g];
        g_w[((size_t)b * 4 + g) * Nn + k] = expf(-(d[j] + bb * bb));
    }
}

// ---------------- K3: fused transpose + levels + jump tables (1024 threads) ----------------
__global__ __launch_bounds__(TP) void k_pretab(const float* __restrict__ feat,
                                               const int* __restrict__ order,
                                               const int* __restrict__ parent) {
    extern __shared__ int sh[];
    int bid = blockIdx.x;
    int tid = threadIdx.x;

    if (bid < 6400) {
        // -------- transpose role: 32x32 tile, 1 element/thread --------
        __shared__ float t[32][33];
        int b = bid / 1600;
        int r2 = bid - b * 1600;
        int c0 = (r2 / 200) * 32;
        int n0 = (r2 % 200) * 32;
        int tx = tid & 31, ty = tid >> 5;
        const float* src = feat + ((size_t)b * CIN + c0) * Nn + n0;
        t[ty][tx] = src[(size_t)ty * Nn + tx];
        __syncthreads();
        float* dst = g_ft + ((size_t)b * Nn + n0) * CIN + c0;
        dst[(size_t)ty * CIN + tx] = t[tx][ty];
        return;
    }

    if (bid < 6404) {
        // -------- levels role --------
        int* a0 = sh;
        int* a1 = sh + Nn;
        int* l0 = sh + 2 * Nn;
        int* l1 = sh + 3 * Nn;
        __shared__ int s_more;
        int b = bid - 6400;
        const int* pp = parent + b * Nn;
        const int* od = order + b * Nn;
        for (int k = tid; k < Nn; k += TP) {
            a0[k] = pp[k];
            l0[k] = (k == 0) ? 0 : 1;
            g_inv[b * Nn + od[k]] = k;
        }
        __syncthreads();
        int* aa = a0; int* ab = a1; int* la = l0; int* lb = l1;
        for (int it = 0; it < 13; ++it) {
            if (tid == 0) s_more = 0;
            __syncthreads();
            int any = 0;
            for (int k = tid; k < Nn; k += TP) {
                int a = aa[k];
                lb[k] = la[k] + la[a];
                int na = aa[a];
                ab[k] = na;
                any |= na;
            }
            if (any) s_more = 1;
            __syncthreads();
            int* tmp = aa; aa = ab; ab = tmp;
            tmp = la; la = lb; lb = tmp;
            if (!s_more) break;
        }
        int* ls = g_ls + b * (Nn + 2);
        for (int k = tid; k < Nn; k += TP) {
            if (k == 0) ls[0] = 0;
            else if (la[k] != la[k - 1]) ls[la[k]] = k;
            if (k == Nn - 1) { g_nlvl[b] = la[k] + 1; ls[la[k] + 1] = Nn; }
        }
        return;
    }

    // -------- tables role: slots 0..7 (strides 1..128) --------
    {
        int b = bid - 6404;
        const int* pp = parent + b * Nn;
        int*    anc = g_janc + (size_t)b * NS * Nn;
        float4* jm4 = g_jm4  + (size_t)b * NS * Nn;
        for (int k = tid; k < Nn; k += TP) {
            anc[k] = pp[k];
            float4 mv;
            mv.x = (k == 0) ? 0.f : g_w[((size_t)b * 4 + 0) * Nn + k];
            mv.y = (k == 0) ? 0.f : g_w[((size_t)b * 4 + 1) * Nn + k];
            mv.z = (k == 0) ? 0.f : g_w[((size_t)b * 4 + 2) * Nn + k];
            mv.w = (k == 0) ? 0.f : g_w[((size_t)b * 4 + 3) * Nn + k];
            jm4[k] = mv;
        }
        __syncthreads();
        for (int s = 1; s < NS; ++s) {
            for (int k = tid; k < Nn; k += TP) {
                int a = anc[(s - 1) * Nn + k];
                anc[s * Nn + k] = anc[(s - 1) * Nn + a];
                float4 mk = jm4[(s - 1) * Nn + k];
                float4 ma = jm4[(s - 1) * Nn + a];
                float4 mo;
                mo.x = mk.x * ma.x; mo.y = mk.y * ma.y;
                mo.z = mk.z * ma.z; mo.w = mk.w * ma.w;
                jm4[s * Nn + k] = mo;
            }
            __syncthreads();
        }
        float* jmP = g_jmP + (size_t)b * NS * Gn * Nn;
        for (int s = 0; s < NS; ++s) {
            for (int k = tid; k < Nn; k += TP) {
                float4 m = jm4[s * Nn + k];
                jmP[(s * Gn + 0) * Nn + k] = m.x;
                jmP[(s * Gn + 1) * Nn + k] = m.y;
                jmP[(s * Gn + 2) * Nn + k] = m.z;
                jmP[(s * Gn + 3) * Nn + k] = m.w;
            }
        }
        int* rs = g_rs + (size_t)b * NS * Nn;
        int* re = g_re + (size_t)b * NS * Nn;
        for (int i = tid; i < NS * Nn; i += TP) { rs[i] = 0; re[i] = 0; }
        __syncthreads();
        for (int s = 0; s < NS; ++s) {
            const int* as = anc + s * Nn;
            for (int j = tid; j < Nn; j += TP) {
                int a = as[j];
                int ap = (j > 0) ? as[j - 1] : -1;
                if (a != ap) {
                    rs[s * Nn + a] = j;
                    if (j > 0) re[s * Nn + ap] = j;
                }
                if (j == Nn - 1) re[s * Nn + a] = Nn;
            }
        }
    }
}

// ---------------- K4: up-sweep — register-primary, scalar multipliers, root-clamped ----------------
// grid (68, Bn): ci<64 feature chunk (g=ci>>4, quad ci&15); ci>=64 norm group g=ci-64 (1ch)
__global__ __launch_bounds__(TU, 1) void k_up(const int* __restrict__ order) {
    extern __shared__ float4 sm[];
    __shared__ int sls[64];
    __shared__ int s_rlo[8], s_rhi[8];
    __shared__ int s_nlvl;
    int ci = blockIdx.x, b = blockIdx.y;
    int g = (ci < 64) ? (ci >> 4) : (ci - 64);
    int qq = ci & 15;
    int tid = threadIdx.x;
    if (tid == 0) s_nlvl = g_nlvl[b];
    __syncthreads();
    int nlvl = s_nlvl;
    int nb = (nlvl + 127) / 128;
    const int* gls = g_ls + b * (Nn + 2);
    for (int i = tid; i <= nb; i += TU) {
        int lev = 128 * i;
        sls[i] = (lev == 0) ? 0 : ((lev >= nlvl) ? Nn : gls[lev]);
    }
    if (tid < 8) {
        int sv = 1 << tid;
        s_rlo[tid] = (sv < nlvl) ? gls[sv] : Nn;
        s_rhi[tid] = (sv < nlvl) ? gls[sv + 1] : Nn;
    }

    // init values in registers
    const int* od = order + b * Nn;
    float4 val[QU];
#pragma unroll
    for (int q = 0; q < QU; ++q) {
        int k = tid + TU * q;
        if (k < Nn) {
            int n = od[k];
            float cf = g_conf[((size_t)b * Nn + n) * 4 + g];
            if (ci < 64) {
                float4 v = *reinterpret_cast<const float4*>(
                    g_ft + ((size_t)b * Nn + n) * CIN + g * 64 + qq * 4);
                val[q] = make_float4(v.x * cf, v.y * cf, v.z * cf, v.w * cf);
            } else {
                val[q] = make_float4(cf, 0.f, 0.f, 0.f);
            }
        } else val[q] = make_float4(0.f, 0.f, 0.f, 0.f);
    }

    const int*   rsb  = g_rs   + (size_t)b * NS * Nn;
    const int*   reb  = g_re   + (size_t)b * NS * Nn;
    const int*   ancb = g_janc + (size_t)b * NS * Nn;
    const float* mPb  = g_jmP  + (size_t)b * NS * Gn * Nn + (size_t)g * Nn;

    // ---- 7 factor passes: publish m_s*val, gather pure-LDS (root clamped) ----
    for (int s = 0; s < 7; ++s) {
        const float* mp = mPb + (size_t)s * Gn * Nn;
        const int* rs = rsb + s * Nn;
        const int* re = reb + s * Nn;
        __syncthreads();
#pragma unroll
        for (int q = 0; q < QU; ++q) {
            int k = tid + TU * q;
            if (k < Nn) {
                float m = __ldg(&mp[k]);
                float4 v = val[q];
                sm[k] = make_float4(m * v.x, m * v.y, m * v.z, m * v.w);
            }
        }
        __syncthreads();
#pragma unroll
        for (int q = 0; q < QU; ++q) {
            int k = tid + TU * q;
            if (k < Nn) {
                int lo, hi;
                if (k == 0) { lo = s_rlo[s]; hi = s_rhi[s]; }
                else        { lo = __ldg(&rs[k]); hi = __ldg(&re[k]); }
                float4 acc = val[q];
                for (int j = lo; j < hi; ++j) {
                    float4 x = sm[j];
                    acc.x += x.x; acc.y += x.y; acc.z += x.z; acc.w += x.w;
                }
                val[q] = acc;
            }
        }
    }

    // ---- stride-128 tail solve, deep -> shallow (root clamped) ----
    {
        const int* rs7 = rsb + 7 * Nn;
        const int* re7 = reb + 7 * Nn;
        const float* m7 = mPb + (size_t)7 * Gn * Nn;
        __syncthreads();
#pragma unroll
        for (int q = 0; q < QU; ++q) {
            int k = tid + TU * q;
            if (k < Nn) {
                float m = __ldg(&m7[k]);
                float4 v = val[q];
                sm[k] = make_float4(m * v.x, m * v.y, m * v.z, m * v.w);
            }
        }
        __syncthreads();
        for (int blk = nb - 2; blk >= 0; --blk) {
            int s0 = sls[blk], e0 = sls[blk + 1];
#pragma unroll
            for (int q = 0; q < QU; ++q) {
                int k = tid + TU * q;
                if (k >= s0 && k < e0) {
                    int lo, hi;
                    if (k == 0) { lo = s_rlo[7]; hi = s_rhi[7]; }
                    else        { lo = __ldg(&rs7[k]); hi = __ldg(&re7[k]); }
                    float4 acc = val[q];
                    for (int j = lo; j < hi; ++j) {
                        float4 x = sm[j];
                        acc.x += x.x; acc.y += x.y; acc.z += x.z; acc.w += x.w;
                    }
                    val[q] = acc;
                    float m = __ldg(&m7[k]);
                    sm[k] = make_float4(m * acc.x, m * acc.y, m * acc.z, m * acc.w);
                }
            }
            __syncthreads();
        }
    }

    // ---- c1 = (1 - w^2) * agg ----
#pragma unroll
    for (int q = 0; q < QU; ++q) {
        int k = tid + TU * q;
        if (k < Nn) {
            float w = __ldg(&mPb[k]);
            float f = 1.f - w * w;
            val[q].x *= f; val[q].y *= f; val[q].z *= f; val[q].w *= f;
        }
    }

    // ---- 7 compose passes ----
    for (int s = 0; s < 7; ++s) {
        const int* anc = ancb + s * Nn;
        const float* mp = mPb + (size_t)s * Gn * Nn;
        __syncthreads();
#pragma unroll
        for (int q = 0; q < QU; ++q) {
            int k = tid + TU * q;
            if (k < Nn) sm[k] = val[q];
        }
        __syncthreads();
#pragma unroll
        for (int q = 0; q < QU; ++q) {
            int k = tid + TU * q;
            if (k < Nn) {
                int a = __ldg(&anc[k]);
                float m = __ldg(&mp[k]);
                float4 ca = sm[a];
                val[q].x += m * ca.x; val[q].y += m * ca.y;
                val[q].z += m * ca.z; val[q].w += m * ca.w;
            }
        }
    }

    // writeback
    if (ci < 64) {
        float4* cc = g_cC + ((size_t)b * NCH + ci) * Nn;
#pragma unroll
        for (int q = 0; q < QU; ++q) {
            int k = tid + TU * q;
            if (k < Nn) cc[k] = val[q];
        }
    } else {
        float* cc = reinterpret_cast<float*>(g_cC + ((size_t)b * NCH + 64) * Nn);
#pragma unroll
        for (int q = 0; q < QU; ++q) {
            int k = tid + TU * q;
            if (k < Nn) cc[k * 4 + g] = val[q].x;
        }
    }
}

// ---------------- K5: strided down-sweep (128 levels per phase) ----------------
__global__ __launch_bounds__(TU, 2) void k_down() {
    extern __shared__ float4 Z[];
    __shared__ int sls[64];
    __shared__ int s_nlvl;
    int ci = blockIdx.x, b = blockIdx.y;
    int tid = threadIdx.x;
    bool norm = (ci == 64);
    int g = norm ? 0 : (ci >> 4);

    if (tid == 0) s_nlvl = g_nlvl[b];
    __syncthreads();
    int nlvl = s_nlvl;
    int nph = (nlvl + 127) / 128;
    const int* gls = g_ls + b * (Nn + 2);
    for (int i = tid; i <= nph; i += TU) {
        int lev = 128 * i;
        sls[i] = (lev == 0) ? 0 : ((lev >= nlvl) ? Nn : gls[lev]);
    }
    __syncthreads();

    float4* cc = g_cC + ((size_t)b * NCH + ci) * Nn;
    const int* aa = g_janc + ((size_t)b * NS + 7) * Nn;
    const float4* m4 = g_jm4 + ((size_t)b * NS + 7) * Nn;
    const float* mP = g_jmP + (size_t)b * NS * Gn * Nn + (size_t)(7 * Gn + g) * Nn;

    for (int t = 0; t < nph; ++t) {
        int s0 = sls[t], e0 = sls[t + 1];
        for (int k = s0 + tid; k < e0; k += TU) {
            float4 cv = __ldg(&cc[k]);
            if (t > 0) {
                int a = __ldg(&aa[k]);
                float4 zp = Z[a];
                if (!norm) {
                    float m = __ldg(&mP[k]);
                    cv.x += m * zp.x; cv.y += m * zp.y;
                    cv.z += m * zp.z; cv.w += m * zp.w;
                } else {
                    float4 m = __ldg(&m4[k]);
                    cv.x += m.x * zp.x; cv.y += m.y * zp.y;
                    cv.z += m.z * zp.z; cv.w += m.w * zp.w;
                }
            }
            Z[k] = cv;
        }
        __syncthreads();
    }
    for (int k = tid; k < Nn; k += TU) cc[k] = Z[k];
}

// ---------------- K6: normalize + un-permute + residual ----------------
__global__ __launch_bounds__(256) void k_final(const float* __restrict__ feat,
                                               const float* __restrict__ gammap,
                                               float* __restrict__ out) {
    __shared__ float tile[32 * 65 * 4];
    __shared__ int kq[32];
    int b = blockIdx.y, n0 = blockIdx.x * 32;
    int tid = threadIdx.x;
    if (tid < 32) kq[tid] = g_inv[b * Nn + n0 + tid];
    __syncthreads();
    float4* tile4 = reinterpret_cast<float4*>(tile);
    for (int i = tid; i < 32 * 65; i += 256) {
        int r = i / 65, ci = i - r * 65;
        tile4[i] = g_cC[((size_t)b * NCH + ci) * Nn + kq[r]];
    }
    __syncthreads();
    float gamma = gammap[0];
    int nl = tid & 31;
    int cg = tid >> 5;
    for (int c = cg; c < 256; c += 8) {
        int gr = c >> 6, j = c & 63;
        float filt = tile[(nl * 65 + gr * 16 + (j >> 2)) * 4 + (j & 3)];
        float nrm  = tile[(nl * 65 + 64) * 4 + gr];
        float res = filt / (EPSV + nrm);
        size_t idx = ((size_t)b * CIN + c) * Nn + n0 + nl;
        out[idx] = fmaf(gamma, res, feat[idx]);
    }
}

// ---------------- launcher ----------------
extern "C" void kernel_launch(void* const* d_in, const int* in_sizes, int n_in,
                              void* d_out, int out_size) {
    const float* feature = (const float*)d_in[0];
    const float* guide   = (const float*)d_in[1];
    const float* We      = (const float*)d_in[2];
    const float* Wc      = (const float*)d_in[3];
    const float* Wg      = (const float*)d_in[4];
    const float* beta    = (const float*)d_in[5];
    const float* gamma   = (const float*)d_in[6];
    const int*   order   = (const int*)d_in[7];
    const int*   parent  = (const int*)d_in[8];
    float* out = (float*)d_out;

    cudaFuncSetAttribute(k_pretab, cudaFuncAttributeMaxDynamicSharedMemorySize, 4 * Nn * 4);
    cudaFuncSetAttribute(k_up,     cudaFuncAttributeMaxDynamicSharedMemorySize, Nn * 16);
    cudaFuncSetAttribute(k_down,   cudaFuncAttributeMaxDynamicSharedMemorySize, Nn * 16);

    // k_up is this module's 4th launch (ncu -s 5 profiles it)
    k_gemm<<<dim3(Nn / 128, Bn, 2), 256>>>(feature, guide, We, Wc, Wg);
    k_w<<<dim3(Nn * 2 / 256, Bn), 256>>>(order, parent, beta);
    k_pretab<<<6408, TP, 4 * Nn * 4>>>(feature, order, parent);
    k_up<<<dim3(68, Bn), TU, Nn * 16>>>(order);
    k_down<<<dim3(NCH, Bn), TU, Nn * 16>>>();
    k_final<<<dim3(Nn / 32, Bn), 256>>>(feature, gamma, out);
}

// round 14
// speedup vs baseline: 1.3338x; 1.0629x over previous
#include <cuda_runtime.h>
#include <math.h>

#define Bn   4
#define CIN  256
#define CE   64
#define Gn   4
#define Hn   80
#define Wn   80
#define Nn   (Hn*Wn)        // 6400
#define NCH  65             // output chunks: 64 feature (4ch) + 1 norm
#define NS   8              // table slots: strides 1,2,4,...,128
#define EPSV 1e-8f
#define TU   384            // threads for k_up
#define QU   17             // ceil(Nn/TU)
#define TD   512            // threads for k_down
#define TP   1024           // threads for k_pretab

// ---------------- static device scratch ----------------
__device__ float  g_ft   [Bn*Nn*CIN];
__device__ float  g_embt [Bn*Nn*CE];
__device__ float  g_gembt[Bn*Nn*CE];
__device__ float  g_conf [Bn*Nn*Gn];
__device__ float  g_w    [Bn*Gn*Nn];
__device__ float4 g_cC   [Bn*NCH*Nn];
__device__ float4 g_jm4  [Bn*NS*Nn];      // multipliers float4 [b][slot][k] (k_down norm path)
__device__ float  g_jmP  [Bn*NS*Gn*Nn];   // multipliers planar [b][slot][g][k]
__device__ int    g_janc [Bn*NS*Nn];
__device__ int2   g_rr   [Bn*NS*Nn];      // packed descendant range {lo, hi}
__device__ int    g_inv  [Bn*Nn];
__device__ int    g_ls   [Bn*(Nn+2)];
__device__ int    g_nlvl [Bn];

// ---------------- packed f32x2 FMA ----------------
__device__ __forceinline__ void ffma2(unsigned long long &d,
                                      unsigned long long a,
                                      unsigned long long b) {
    asm("fma.rn.f32x2 %0, %1, %2, %0;" : "+l"(d) : "l"(a), "l"(b));
}

// ---------------- K1: skinny GEMMs via packed f32x2 FMA ----------------
__global__ __launch_bounds__(256) void k_gemm(const float* __restrict__ feat,
                                              const float* __restrict__ guide,
                                              const float* __restrict__ We,
                                              const float* __restrict__ Wc,
                                              const float* __restrict__ Wg) {
    __shared__ char smraw[34816];
    float*  xs = reinterpret_cast<float*>(smraw);
    float2* ws = reinterpret_cast<float2*>(smraw + 16384);
    float*  stage = reinterpret_cast<float*>(smraw);

    int tid = threadIdx.x;
    int os = tid >> 5;
    int nq = tid & 31;
    int n0 = blockIdx.x * 128;
    int b  = blockIdx.y;
    int path = blockIdx.z;

    const float* X = (path == 0 ? feat : guide) + (size_t)b * CIN * Nn;

    unsigned long long acc[9][2];
#pragma unroll
    for (int j = 0; j < 9; ++j) { acc[j][0] = 0ull; acc[j][1] = 0ull; }

    for (int kc = 0; kc < 256; kc += 32) {
        const float* Xb = X + (size_t)kc * Nn + n0;
#pragma unroll
        for (int i = tid; i < 1024; i += 256) {
            int kk = i >> 5, c4 = i & 31;
            *reinterpret_cast<float4*>(&xs[kk * 128 + c4 * 4]) =
                *reinterpret_cast<const float4*>(&Xb[(size_t)kk * Nn + c4 * 4]);
        }
#pragma unroll
        for (int i = tid; i < 2304; i += 256) {
            int o = i >> 5, kk = i & 31;
            float v = 0.f;
            if (path == 0) {
                if (o < 64)       v = We[o * 256 + kc + kk];
                else if (o < 68)  v = Wc[(o - 64) * 256 + kc + kk];
            } else {
                if (o < 64)       v = Wg[o * 256 + kc + kk];
            }
            ws[i] = make_float2(v, v);
        }
        __syncthreads();
#pragma unroll 2
        for (int kk = 0; kk < 32; ++kk) {
            float4 x4 = *reinterpret_cast<const float4*>(&xs[kk * 128 + nq * 4]);
            unsigned long long xlo = *reinterpret_cast<unsigned long long*>(&x4.x);
            unsigned long long xhi = *reinterpret_cast<unsigned long long*>(&x4.z);
#pragma unroll
            for (int j = 0; j < 9; ++j) {
                float2 wv = ws[(os * 9 + j) * 32 + kk];
                unsigned long long wp = *reinterpret_cast<unsigned long long*>(&wv);
                ffma2(acc[j][0], xlo, wp);
                ffma2(acc[j][1], xhi, wp);
            }
        }
        __syncthreads();
    }
#pragma unroll
    for (int j = 0; j < 9; ++j) {
        int o = os * 9 + j;
        if (o < 68) {
            float2 lo = *reinterpret_cast<float2*>(&acc[j][0]);
            float2 hi = *reinterpret_cast<float2*>(&acc[j][1]);
            stage[(nq * 4 + 0) * 68 + o] = lo.x;
            stage[(nq * 4 + 1) * 68 + o] = lo.y;
            stage[(nq * 4 + 2) * 68 + o] = hi.x;
            stage[(nq * 4 + 3) * 68 + o] = hi.y;
        }
    }
    __syncthreads();
    float* outt = (path == 0) ? g_embt : g_gembt;
#pragma unroll
    for (int i = tid; i < 2048; i += 256) {
        int n = i >> 4, c4 = i & 15;
        float4 v = *reinterpret_cast<float4*>(&stage[n * 68 + c4 * 4]);
        *reinterpret_cast<float4*>(&outt[((size_t)b * Nn + n0 + n) * 64 + c4 * 4]) = v;
    }
    if (path == 0) {
#pragma unroll
        for (int i = tid; i < 512; i += 256) {
            int n = i >> 2, gg = i & 3;
            float x = stage[n * 68 + 64 + gg];
            g_conf[((size_t)b * Nn + n0 + n) * 4 + gg] = 1.f / (1.f + expf(-x));
        }
    }
}

// ---------------- K2: edge weights, 2 threads per node ----------------
__global__ __launch_bounds__(256) void k_w(const int* __restrict__ order,
                                           const int* __restrict__ parent,
                                           const float* __restrict__ beta) {
    int b = blockIdx.y;
    int idx = blockIdx.x * 256 + threadIdx.x;
    int k = idx >> 1, half = idx & 1;
    if (k >= Nn) return;
    int n1 = order[b * Nn + k];
    int p  = parent[b * Nn + k];
    int n0 = order[b * Nn + p];
    int coff = half * 32;
    const float4* e1 = reinterpret_cast<const float4*>(g_embt  + ((size_t)b * Nn + n1) * 64 + coff);
    const float4* e0 = reinterpret_cast<const float4*>(g_embt  + ((size_t)b * Nn + n0) * 64 + coff);
    const float4* q1 = reinterpret_cast<const float4*>(g_gembt + ((size_t)b * Nn + n1) * 64 + coff);
    const float4* q0 = reinterpret_cast<const float4*>(g_gembt + ((size_t)b * Nn + n0) * 64 + coff);
    float d[2] = {0.f, 0.f};
#pragma unroll
    for (int i = 0; i < 8; ++i) {
        float4 a = e1[i], c = e0[i];
        float dx = a.x - c.x, dy = a.y - c.y, dz = a.z - c.z, dw = a.w - c.w;
        d[i >> 2] += dx * dx + dy * dy + dz * dz + dw * dw;
    }
#pragma unroll
    for (int i = 0; i < 8; ++i) {
        float4 a = q1[i], c = q0[i];
        float dx = a.x - c.x, dy = a.y - c.y, dz = a.z - c.z, dw = a.w - c.w;
        d[i >> 2] += dx * dx + dy * dy + dz * dz + dw * dw;
    }
#pragma unroll
    for (int j = 0; j < 2; ++j) {
        int g = half * 2 + j;
        float bb = beta[g];
        g_w[((size_t)b * 4 + g) * Nn + k] = expf(-(d[j] + bb * bb));
    }
}

// ---------------- K3: fused transpose + levels + jump tables ----------------
__global__ __launch_bounds__(TP) void k_pretab(const float* __restrict__ feat,
                                               const int* __restrict__ order,
                                               const int* __restrict__ parent) {
    extern __shared__ int sh[];
    int bid = blockIdx.x;
    int tid = threadIdx.x;

    if (bid < 6400) {
        __shared__ float t[32][33];
        int b = bid / 1600;
        int r2 = bid - b * 1600;
        int c0 = (r2 / 200) * 32;
        int n0 = (r2 % 200) * 32;
        int tx = tid & 31, ty = tid >> 5;
        const float* src = feat + ((size_t)b * CIN + c0) * Nn + n0;
        t[ty][tx] = src[(size_t)ty * Nn + tx];
        __syncthreads();
        float* dst = g_ft + ((size_t)b * Nn + n0) * CIN + c0;
        dst[(size_t)ty * CIN + tx] = t[tx][ty];
        return;
    }

    if (bid < 6404) {
        int* a0 = sh;
        int* a1 = sh + Nn;
        int* l0 = sh + 2 * Nn;
        int* l1 = sh + 3 * Nn;
        __shared__ int s_more;
        int b = bid - 6400;
        const int* pp = parent + b * Nn;
        const int* od = order + b * Nn;
        for (int k = tid; k < Nn; k += TP) {
            a0[k] = pp[k];
            l0[k] = (k == 0) ? 0 : 1;
            g_inv[b * Nn + od[k]] = k;
        }
        __syncthreads();
        int* aa = a0; int* ab = a1; int* la = l0; int* lb = l1;
        for (int it = 0; it < 13; ++it) {
            if (tid == 0) s_more = 0;
            __syncthreads();
            int any = 0;
            for (int k = tid; k < Nn; k += TP) {
                int a = aa[k];
                lb[k] = la[k] + la[a];
                int na = aa[a];
                ab[k] = na;
                any |= na;
            }
            if (any) s_more = 1;
            __syncthreads();
            int* tmp = aa; aa = ab; ab = tmp;
            tmp = la; la = lb; lb = tmp;
            if (!s_more) break;
        }
        int* ls = g_ls + b * (Nn + 2);
        for (int k = tid; k < Nn; k += TP) {
            if (k == 0) ls[0] = 0;
            else if (la[k] != la[k - 1]) ls[la[k]] = k;
            if (k == Nn - 1) { g_nlvl[b] = la[k] + 1; ls[la[k] + 1] = Nn; }
        }
        return;
    }

    // -------- tables role: slots 0..7 (strides 1..128) + packed ranges --------
    {
        int b = bid - 6404;
        const int* pp = parent + b * Nn;
        int*    anc = g_janc + (size_t)b * NS * Nn;
        float4* jm4 = g_jm4  + (size_t)b * NS * Nn;
        for (int k = tid; k < Nn; k += TP) {
            anc[k] = pp[k];
            float4 mv;
            mv.x = (k == 0) ? 0.f : g_w[((size_t)b * 4 + 0) * Nn + k];
            mv.y = (k == 0) ? 0.f : g_w[((size_t)b * 4 + 1) * Nn + k];
            mv.z = (k == 0) ? 0.f : g_w[((size_t)b * 4 + 2) * Nn + k];
            mv.w = (k == 0) ? 0.f : g_w[((size_t)b * 4 + 3) * Nn + k];
            jm4[k] = mv;
        }
        __syncthreads();
        for (int s = 1; s < NS; ++s) {
            for (int k = tid; k < Nn; k += TP) {
                int a = anc[(s - 1) * Nn + k];
                anc[s * Nn + k] = anc[(s - 1) * Nn + a];
                float4 mk = jm4[(s - 1) * Nn + k];
                float4 ma = jm4[(s - 1) * Nn + a];
                float4 mo;
                mo.x = mk.x * ma.x; mo.y = mk.y * ma.y;
                mo.z = mk.z * ma.z; mo.w = mk.w * ma.w;
                jm4[s * Nn + k] = mo;
            }
            __syncthreads();
        }
        float* jmP = g_jmP + (size_t)b * NS * Gn * Nn;
        for (int s = 0; s < NS; ++s) {
            for (int k = tid; k < Nn; k += TP) {
                float4 m = jm4[s * Nn + k];
                jmP[(s * Gn + 0) * Nn + k] = m.x;
                jmP[(s * Gn + 1) * Nn + k] = m.y;
                jmP[(s * Gn + 2) * Nn + k] = m.z;
                jmP[(s * Gn + 3) * Nn + k] = m.w;
            }
        }
        // ranges: scratch in smem (reuse sh as rs/re), then pack to int2
        int* rs = sh;          // [Nn]
        int* re = sh + Nn;     // [Nn]
        int2* rr = g_rr + (size_t)b * NS * Nn;
        for (int s = 0; s < NS; ++s) {
            const int* as = anc + s * Nn;
            for (int i = tid; i < Nn; i += TP) { rs[i] = 0; re[i] = 0; }
            __syncthreads();
            for (int j = tid; j < Nn; j += TP) {
                int a = as[j];
                int ap = (j > 0) ? as[j - 1] : -1;
                if (a != ap) {
                    rs[a] = j;
                    if (j > 0) re[ap] = j;
                }
                if (j == Nn - 1) re[a] = Nn;
            }
            __syncthreads();
            for (int k = tid; k < Nn; k += TP)
                rr[s * Nn + k] = make_int2(rs[k], re[k]);
            __syncthreads();
        }
    }
}

// ---------------- K4: up-sweep — paired chunks, register-primary, root-clamped ----------------
// grid (34, Bn): p<32 feature pair (g=p>>3, quads p&7 and (p&7)+8); p>=32 norm pair (groups 2(p-32), +1)
__global__ __launch_bounds__(TU) void k_up(const int* __restrict__ order) {
    extern __shared__ float4 smb[];
    float4* bufA = smb;        // [Nn]
    float4* bufB = smb + Nn;   // [Nn]
    __shared__ int sls[64];
    __shared__ int s_rlo[8], s_rhi[8];
    __shared__ int s_nlvl;
    int p = blockIdx.x, b = blockIdx.y;
    bool isNorm = (p >= 32);
    int gA, gB, qqA, qqB;
    if (!isNorm) { gA = p >> 3; gB = gA; qqA = p & 7; qqB = qqA + 8; }
    else         { gA = (p - 32) * 2; gB = gA + 1; qqA = 0; qqB = 0; }
    int tid = threadIdx.x;
    if (tid == 0) s_nlvl = g_nlvl[b];
    __syncthreads();
    int nlvl = s_nlvl;
    int nb = (nlvl + 127) / 128;
    const int* gls = g_ls + b * (Nn + 2);
    for (int i = tid; i <= nb; i += TU) {
        int lev = 128 * i;
        sls[i] = (lev == 0) ? 0 : ((lev >= nlvl) ? Nn : gls[lev]);
    }
    if (tid < 8) {
        int sv = 1 << tid;
        s_rlo[tid] = (sv < nlvl) ? gls[sv] : Nn;
        s_rhi[tid] = (sv < nlvl) ? gls[sv + 1] : Nn;
    }

    // init values in registers
    const int* od = order + b * Nn;
    float4 vA[QU], vB[QU];
#pragma unroll
    for (int q = 0; q < QU; ++q) {
        int k = tid + TU * q;
        if (k < Nn) {
            int n = od[k];
            if (!isNorm) {
                float cf = g_conf[((size_t)b * Nn + n) * 4 + gA];
                const float* fr = g_ft + ((size_t)b * Nn + n) * CIN + gA * 64;
                float4 a = *reinterpret_cast<const float4*>(fr + qqA * 4);
                float4 c = *reinterpret_cast<const float4*>(fr + qqB * 4);
                vA[q] = make_float4(a.x * cf, a.y * cf, a.z * cf, a.w * cf);
                vB[q] = make_float4(c.x * cf, c.y * cf, c.z * cf, c.w * cf);
            } else {
                const float* cf4 = g_conf + ((size_t)b * Nn + n) * 4;
                vA[q] = make_float4(cf4[gA], 0.f, 0.f, 0.f);
                vB[q] = make_float4(cf4[gB], 0.f, 0.f, 0.f);
            }
        } else { vA[q] = make_float4(0.f,0.f,0.f,0.f); vB[q] = vA[q]; }
    }

    const int2*  rrb  = g_rr   + (size_t)b * NS * Nn;
    const int*   ancb = g_janc + (size_t)b * NS * Nn;
    const float* mA   = g_jmP  + (size_t)b * NS * Gn * Nn + (size_t)gA * Nn;
    const float* mB   = g_jmP  + (size_t)b * NS * Gn * Nn + (size_t)gB * Nn;

    // ---- 7 factor passes ----
    for (int s = 0; s < 7; ++s) {
        const float* mAs = mA + (size_t)s * Gn * Nn;
        const float* mBs = mB + (size_t)s * Gn * Nn;
        const int2* rr = rrb + s * Nn;
        __syncthreads();
#pragma unroll
        for (int q = 0; q < QU; ++q) {
            int k = tid + TU * q;
            if (k < Nn) {
                float ma = __ldg(&mAs[k]);
                float mb = __ldg(&mBs[k]);
                float4 a = vA[q], c = vB[q];
                bufA[k] = make_float4(ma * a.x, ma * a.y, ma * a.z, ma * a.w);
                bufB[k] = make_float4(mb * c.x, mb * c.y, mb * c.z, mb * c.w);
            }
        }
        __syncthreads();
#pragma unroll
        for (int q = 0; q < QU; ++q) {
            int k = tid + TU * q;
            if (k < Nn) {
                int lo, hi;
                if (k == 0) { lo = s_rlo[s]; hi = s_rhi[s]; }
                else { int2 r = __ldg(&rr[k]); lo = r.x; hi = r.y; }
                float4 aA = vA[q], aB = vB[q];
                for (int j = lo; j < hi; ++j) {
                    float4 xa = bufA[j];
                    float4 xb = bufB[j];
                    aA.x += xa.x; aA.y += xa.y; aA.z += xa.z; aA.w += xa.w;
                    aB.x += xb.x; aB.y += xb.y; aB.z += xb.z; aB.w += xb.w;
                }
                vA[q] = aA; vB[q] = aB;
            }
        }
    }

    // ---- stride-128 tail solve, deep -> shallow ----
    {
        const int2* rr7 = rrb + 7 * Nn;
        const float* mA7 = mA + (size_t)7 * Gn * Nn;
        const float* mB7 = mB + (size_t)7 * Gn * Nn;
        __syncthreads();
#pragma unroll
        for (int q = 0; q < QU; ++q) {
            int k = tid + TU * q;
            if (k < Nn) {
                float ma = __ldg(&mA7[k]);
                float mb = __ldg(&mB7[k]);
                float4 a = vA[q], c = vB[q];
                bufA[k] = make_float4(ma * a.x, ma * a.y, ma * a.z, ma * a.w);
                bufB[k] = make_float4(mb * c.x, mb * c.y, mb * c.z, mb * c.w);
            }
        }
        __syncthreads();
        for (int blk = nb - 2; blk >= 0; --blk) {
            int s0 = sls[blk], e0 = sls[blk + 1];
#pragma unroll
            for (int q = 0; q < QU; ++q) {
                int k = tid + TU * q;
                if (k >= s0 && k < e0) {
                    int lo, hi;
                    if (k == 0) { lo = s_rlo[7]; hi = s_rhi[7]; }
                    else { int2 r = __ldg(&rr7[k]); lo = r.x; hi = r.y; }
                    float4 aA = vA[q], aB = vB[q];
                    for (int j = lo; j < hi; ++j) {
                        float4 xa = bufA[j];
                        float4 xb = bufB[j];
                        aA.x += xa.x; aA.y += xa.y; aA.z += xa.z; aA.w += xa.w;
                        aB.x += xb.x; aB.y += xb.y; aB.z += xb.z; aB.w += xb.w;
                    }
                    vA[q] = aA; vB[q] = aB;
                    float ma = __ldg(&mA7[k]);
                    float mb = __ldg(&mB7[k]);
                    bufA[k] = make_float4(ma * aA.x, ma * aA.y, ma * aA.z, ma * aA.w);
                    bufB[k] = make_float4(mb * aB.x, mb * aB.y, mb * aB.z, mb * aB.w);
                }
            }
            __syncthreads();
        }
    }

    // ---- c1 = (1 - w^2) * agg ----
#pragma unroll
    for (int q = 0; q < QU; ++q) {
        int k = tid + TU * q;
        if (k < Nn) {
            float wa = __ldg(&mA[k]);
            float wb = __ldg(&mB[k]);
            float fa = 1.f - wa * wa;
            float fb = 1.f - wb * wb;
            vA[q].x *= fa; vA[q].y *= fa; vA[q].z *= fa; vA[q].w *= fa;
            vB[q].x *= fb; vB[q].y *= fb; vB[q].z *= fb; vB[q].w *= fb;
        }
    }

    // ---- 7 compose passes ----
    for (int s = 0; s < 7; ++s) {
        const int* anc = ancb + s * Nn;
        const float* mAs = mA + (size_t)s * Gn * Nn;
        const float* mBs = mB + (size_t)s * Gn * Nn;
        __syncthreads();
#pragma unroll
        for (int q = 0; q < QU; ++q) {
            int k = tid + TU * q;
            if (k < Nn) { bufA[k] = vA[q]; bufB[k] = vB[q]; }
        }
        __syncthreads();
#pragma unroll
        for (int q = 0; q < QU; ++q) {
            int k = tid + TU * q;
            if (k < Nn) {
                int a = __ldg(&anc[k]);
                float ma = __ldg(&mAs[k]);
                float mb = __ldg(&mBs[k]);
                float4 ca = bufA[a];
                float4 cb = bufB[a];
                vA[q].x += ma * ca.x; vA[q].y += ma * ca.y;
                vA[q].z += ma * ca.z; vA[q].w += ma * ca.w;
                vB[q].x += mb * cb.x; vB[q].y += mb * cb.y;
                vB[q].z += mb * cb.z; vB[q].w += mb * cb.w;
            }
        }
    }

    // writeback
    if (!isNorm) {
        float4* ccA = g_cC + ((size_t)b * NCH + gA * 16 + qqA) * Nn;
        float4* ccB = g_cC + ((size_t)b * NCH + gA * 16 + qqB) * Nn;
#pragma unroll
        for (int q = 0; q < QU; ++q) {
            int k = tid + TU * q;
            if (k < Nn) { ccA[k] = vA[q]; ccB[k] = vB[q]; }
        }
    } else {
        float* cc = reinterpret_cast<float*>(g_cC + ((size_t)b * NCH + 64) * Nn);
#pragma unroll
        for (int q = 0; q < QU; ++q) {
            int k = tid + TU * q;
            if (k < Nn) { cc[k * 4 + gA] = vA[q].x; cc[k * 4 + gB] = vB[q].x; }
        }
    }
}

// ---------------- K5: strided down-sweep (128 levels per phase) ----------------
__global__ __launch_bounds__(TD, 2) void k_down() {
    extern __shared__ float4 Z[];
    __shared__ int sls[64];
    __shared__ int s_nlvl;
    int ci = blockIdx.x, b = blockIdx.y;
    int tid = threadIdx.x;
    bool norm = (ci == 64);
    int g = norm ? 0 : (ci >> 4);

    if (tid == 0) s_nlvl = g_nlvl[b];
    __syncthreads();
    int nlvl = s_nlvl;
    int nph = (nlvl + 127) / 128;
    const int* gls = g_ls + b * (Nn + 2);
    for (int i = tid; i <= nph; i += TD) {
        int lev = 128 * i;
        sls[i] = (lev == 0) ? 0 : ((lev >= nlvl) ? Nn : gls[lev]);
    }
    __syncthreads();

    float4* cc = g_cC + ((size_t)b * NCH + ci) * Nn;
    const int* aa = g_janc + ((size_t)b * NS + 7) * Nn;
    const float4* m4 = g_jm4 + ((size_t)b * NS + 7) * Nn;
    const float* mP = g_jmP + (size_t)b * NS * Gn * Nn + (size_t)(7 * Gn + g) * Nn;

    for (int t = 0; t < nph; ++t) {
        int s0 = sls[t], e0 = sls[t + 1];
        for (int k = s0 + tid; k < e0; k += TD) {
            float4 cv = __ldg(&cc[k]);
            if (t > 0) {
                int a = __ldg(&aa[k]);
                float4 zp = Z[a];
                if (!norm) {
                    float m = __ldg(&mP[k]);
                    cv.x += m * zp.x; cv.y += m * zp.y;
                    cv.z += m * zp.z; cv.w += m * zp.w;
                } else {
                    float4 m = __ldg(&m4[k]);
                    cv.x += m.x * zp.x; cv.y += m.y * zp.y;
                    cv.z += m.z * zp.z; cv.w += m.w * zp.w;
                }
            }
            Z[k] = cv;
        }
        __syncthreads();
    }
    for (int k = tid; k < Nn; k += TD) cc[k] = Z[k];
}

// ---------------- K6: normalize + un-permute + residual ----------------
__global__ __launch_bounds__(256) void k_final(const float* __restrict__ feat,
                                               const float* __restrict__ gammap,
                                               float* __restrict__ out) {
    __shared__ float tile[32 * 65 * 4];
    __shared__ int kq[32];
    int b = blockIdx.y, n0 = blockIdx.x * 32;
    int tid = threadIdx.x;
    if (tid < 32) kq[tid] = g_inv[b * Nn + n0 + tid];
    __syncthreads();
    float4* tile4 = reinterpret_cast<float4*>(tile);
    for (int i = tid; i < 32 * 65; i += 256) {
        int r = i / 65, ci = i - r * 65;
        tile4[i] = g_cC[((size_t)b * NCH + ci) * Nn + kq[r]];
    }
    __syncthreads();
    float gamma = gammap[0];
    int nl = tid & 31;
    int cg = tid >> 5;
    for (int c = cg; c < 256; c += 8) {
        int gr = c >> 6, j = c & 63;
        float filt = tile[(nl * 65 + gr * 16 + (j >> 2)) * 4 + (j & 3)];
        float nrm  = tile[(nl * 65 + 64) * 4 + gr];
        float res = filt / (EPSV + nrm);
        size_t idx = ((size_t)b * CIN + c) * Nn + n0 + nl;
        out[idx] = fmaf(gamma, res, feat[idx]);
    }
}

// ---------------- launcher ----------------
extern "C" void kernel_launch(void* const* d_in, const int* in_sizes, int n_in,
                              void* d_out, int out_size) {
    const float* feature = (const float*)d_in[0];
    const float* guide   = (const float*)d_in[1];
    const float* We      = (const float*)d_in[2];
    const float* Wc      = (const float*)d_in[3];
    const float* Wg      = (const float*)d_in[4];
    const float* beta    = (const float*)d_in[5];
    const float* gamma   = (const float*)d_in[6];
    const int*   order   = (const int*)d_in[7];
    const int*   parent  = (const int*)d_in[8];
    float* out = (float*)d_out;

    cudaFuncSetAttribute(k_pretab, cudaFuncAttributeMaxDynamicSharedMemorySize, 4 * Nn * 4);
    cudaFuncSetAttribute(k_up,     cudaFuncAttributeMaxDynamicSharedMemorySize, 2 * Nn * 16);
    cudaFuncSetAttribute(k_down,   cudaFuncAttributeMaxDynamicSharedMemorySize, Nn * 16);

    // k_up is this module's 4th launch (ncu -s 5 profiles it)
    k_gemm<<<dim3(Nn / 128, Bn, 2), 256>>>(feature, guide, We, Wc, Wg);
    k_w<<<dim3(Nn * 2 / 256, Bn), 256>>>(order, parent, beta);
    k_pretab<<<6408, TP, 4 * Nn * 4>>>(feature, order, parent);
    k_up<<<dim3(34, Bn), TU, 2 * Nn * 16>>>(order);
    k_down<<<dim3(NCH, Bn), TD, Nn * 16>>>();
    k_final<<<dim3(Nn / 32, Bn), 256>>>(feature, gamma, out);
}